// round 8
// baseline (speedup 1.0000x reference)
#include <cuda_runtime.h>
#include <cstdint>
#include <math.h>

#define BB 2
#define SS 2048
#define DD 1024
#define HH 16
#define HW 64
#define MM (BB*SS)   // 4096

// ---------------- scratch (no cudaMalloc allowed) ---------------------------
__device__ float g_Q[(size_t)MM * DD];                 // 16 MB
__device__ float g_K[(size_t)MM * DD];                 // 16 MB
__device__ float g_V[(size_t)MM * DD];                 // 16 MB

// ---------------- tf32 helpers (non-arch-specific PTX only) -----------------
__device__ __forceinline__ uint32_t f2tf32(float x) {
    uint32_t u; asm("cvt.rna.tf32.f32 %0, %1;" : "=r"(u) : "f"(x)); return u;
}

__device__ __forceinline__ void mma_tf32(float c[4],
                                         uint32_t a0, uint32_t a1, uint32_t a2, uint32_t a3,
                                         uint32_t b0, uint32_t b1) {
    asm volatile(
        "mma.sync.aligned.m16n8k8.row.col.f32.tf32.tf32.f32 "
        "{%0,%1,%2,%3}, {%4,%5,%6,%7}, {%8,%9}, {%0,%1,%2,%3};"
        : "+f"(c[0]), "+f"(c[1]), "+f"(c[2]), "+f"(c[3])
        : "r"(a0), "r"(a1), "r"(a2), "r"(a3), "r"(b0), "r"(b1));
}

// ---------------- fast exp on the FFMA pipe ---------------------------------
__device__ __forceinline__ float fexp(float x) {
    float y = fmaxf(x * 1.4426950408889634f, -126.0f);
    float n = rintf(y);
    float f = y - n;
    float p =              1.5403530393381606e-4f;
    p = fmaf(p, f, 1.3333558146428443e-3f);
    p = fmaf(p, f, 9.6181291076284772e-3f);
    p = fmaf(p, f, 5.5504108664821580e-2f);
    p = fmaf(p, f, 2.4022650695910071e-1f);
    p = fmaf(p, f, 6.9314718055994531e-1f);
    p = fmaf(p, f, 1.0f);
    int e = (((int)n) + 127) << 23;
    return p * __int_as_float(e);
}

// ============================================================================
// K1: tf32 mma.sync GEMM — all three projections in one launch (z = 0,1,2)
// ============================================================================
#define BK 32
#define ASTR 36

__global__ void __launch_bounds__(256)
gemm_tf32(const float* __restrict__ A,
          const float* __restrict__ Wq, const float* __restrict__ bq,
          const float* __restrict__ Wk, const float* __restrict__ bk,
          const float* __restrict__ Wv, const float* __restrict__ bv) {
    const int which = blockIdx.z;
    const float* W    = (which == 0) ? Wq : (which == 1) ? Wk : Wv;
    const float* bias = (which == 0) ? bq : (which == 1) ? bk : bv;
    float* C          = (which == 0) ? g_Q : (which == 1) ? g_K : g_V;

    __shared__ uint32_t sA[128 * ASTR];
    __shared__ uint32_t sB[128 * ASTR];

    const int tid  = threadIdx.x;
    const int wid  = tid >> 5;
    const int lane = tid & 31;
    const int grp  = lane >> 2;
    const int qid  = lane & 3;
    const int m0 = blockIdx.y * 128;
    const int n0 = blockIdx.x * 128;
    const int warp_m = (wid & 1) * 64;
    const int warp_n = (wid >> 1) * 32;

    float acc[4][4][4];
#pragma unroll
    for (int mt = 0; mt < 4; mt++)
#pragma unroll
        for (int nt = 0; nt < 4; nt++)
#pragma unroll
            for (int r = 0; r < 4; r++) acc[mt][nt][r] = 0.f;

    for (int k0 = 0; k0 < DD; k0 += BK) {
#pragma unroll
        for (int t = 0; t < 4; t++) {
            int idx = tid + t * 256;
            int row = idx >> 3;
            int c4  = idx & 7;
            float4 va = *(const float4*)(A + (size_t)(m0 + row) * DD + k0 + c4 * 4);
            *(uint4*)(sA + row * ASTR + c4 * 4) =
                make_uint4(f2tf32(va.x), f2tf32(va.y), f2tf32(va.z), f2tf32(va.w));
            float4 vb = *(const float4*)(W + (size_t)(n0 + row) * DD + k0 + c4 * 4);
            *(uint4*)(sB + row * ASTR + c4 * 4) =
                make_uint4(f2tf32(vb.x), f2tf32(vb.y), f2tf32(vb.z), f2tf32(vb.w));
        }
        __syncthreads();

#pragma unroll
        for (int ks = 0; ks < BK / 8; ks++) {
            const int kk = ks * 8;
            uint32_t af[4][4], bf[4][2];
#pragma unroll
            for (int mt = 0; mt < 4; mt++) {
                const uint32_t* ap = sA + (warp_m + mt * 16 + grp) * ASTR + kk + qid;
                af[mt][0] = ap[0];
                af[mt][1] = ap[8 * ASTR];
                af[mt][2] = ap[4];
                af[mt][3] = ap[8 * ASTR + 4];
            }
#pragma unroll
            for (int nt = 0; nt < 4; nt++) {
                const uint32_t* bp = sB + (warp_n + nt * 8 + grp) * ASTR + kk + qid;
                bf[nt][0] = bp[0];
                bf[nt][1] = bp[4];
            }
#pragma unroll
            for (int mt = 0; mt < 4; mt++)
#pragma unroll
                for (int nt = 0; nt < 4; nt++)
                    mma_tf32(acc[mt][nt], af[mt][0], af[mt][1], af[mt][2], af[mt][3],
                             bf[nt][0], bf[nt][1]);
        }
        __syncthreads();
    }

#pragma unroll
    for (int mt = 0; mt < 4; mt++) {
#pragma unroll
        for (int nt = 0; nt < 4; nt++) {
            int col = n0 + warp_n + nt * 8 + 2 * qid;
            float bx = bias[col], by = bias[col + 1];
            int r0 = m0 + warp_m + mt * 16 + grp;
            *(float2*)(C + (size_t)r0 * DD + col) =
                make_float2(acc[mt][nt][0] + bx, acc[mt][nt][1] + by);
            *(float2*)(C + (size_t)(r0 + 8) * DD + col) =
                make_float2(acc[mt][nt][2] + bx, acc[mt][nt][3] + by);
        }
    }
}

// ============================================================================
// K2: fused attention — pass1 (Z1) + pass2 (recompute, transform, PV)
// CTA: 128 q rows of one (b,h). 8 warps.
// smem: Qs[128][68], Ks[128][68], Ts[128][132] (tf32), Vs[128][72] (tf32)
// Ts stride 132 (>=128 cols!): PV fragment reads bank = 4*grp+qid, conflict-free.
// ============================================================================
#define QST 68
#define TST 132
#define VST 72

__global__ void __launch_bounds__(256)
attn_fused_mma(float* __restrict__ out) {
    extern __shared__ uint32_t dsm[];
    uint32_t* Qs = dsm;                            // [128][QST]
    uint32_t* Ks = dsm + 128 * QST;                // [128][QST]
    uint32_t* Ts = dsm + 2 * 128 * QST;            // [128][TST]
    uint32_t* Vs = dsm + 2 * 128 * QST + 128 * TST; // [128][VST]
    __shared__ float sz[4][128];
    __shared__ float zbuf[128];

    const int bh = blockIdx.y;
    const int b  = bh >> 4, h = bh & 15;
    const int q0 = blockIdx.x * 128;
    const int tid  = threadIdx.x;
    const int wid  = tid >> 5;
    const int lane = tid & 31;
    const int grp  = lane >> 2;
    const int qid  = lane & 3;
    const int widm = wid & 1, widn = wid >> 1;
    const int warp_m = widm * 64, warp_n = widn * 32;

    // Q tile [128][64] -> tf32 smem (persistent)
#pragma unroll
    for (int t = 0; t < 8; t++) {
        int idx = tid + t * 256;
        int row = idx >> 4;
        int c4  = idx & 15;
        float4 v = *(const float4*)(g_Q + (size_t)(b*SS + q0 + row) * DD + h*HW + c4*4);
        *(uint4*)(Qs + row * QST + c4 * 4) =
            make_uint4(f2tf32(v.x), f2tf32(v.y), f2tf32(v.z), f2tf32(v.w));
    }

    // ======================= PASS 1: Z1 =====================================
    float zlo[4] = {0.f,0.f,0.f,0.f}, zhi[4] = {0.f,0.f,0.f,0.f};

    for (int n0 = 0; n0 < SS; n0 += 128) {
        __syncthreads();
#pragma unroll
        for (int t = 0; t < 8; t++) {
            int idx = tid + t * 256;
            int row = idx >> 4;
            int c4  = idx & 15;
            float4 v = *(const float4*)(g_K + (size_t)(b*SS + n0 + row) * DD + h*HW + c4*4);
            *(uint4*)(Ks + row * QST + c4 * 4) =
                make_uint4(f2tf32(v.x), f2tf32(v.y), f2tf32(v.z), f2tf32(v.w));
        }
        __syncthreads();

        float acc[4][4][4];
#pragma unroll
        for (int mt = 0; mt < 4; mt++)
#pragma unroll
            for (int nt = 0; nt < 4; nt++)
#pragma unroll
                for (int r = 0; r < 4; r++) acc[mt][nt][r] = 0.f;

#pragma unroll
        for (int ks = 0; ks < 8; ks++) {
            const int kk = ks * 8;
            uint32_t af[4][4], bf[4][2];
#pragma unroll
            for (int mt = 0; mt < 4; mt++) {
                const uint32_t* ap = Qs + (warp_m + mt * 16 + grp) * QST + kk + qid;
                af[mt][0] = ap[0];
                af[mt][1] = ap[8 * QST];
                af[mt][2] = ap[4];
                af[mt][3] = ap[8 * QST + 4];
            }
#pragma unroll
            for (int nt = 0; nt < 4; nt++) {
                const uint32_t* bp = Ks + (warp_n + nt * 8 + grp) * QST + kk + qid;
                bf[nt][0] = bp[0];
                bf[nt][1] = bp[4];
            }
#pragma unroll
            for (int mt = 0; mt < 4; mt++)
#pragma unroll
                for (int nt = 0; nt < 4; nt++)
                    mma_tf32(acc[mt][nt], af[mt][0], af[mt][1], af[mt][2], af[mt][3],
                             bf[nt][0], bf[nt][1]);
        }

#pragma unroll
        for (int mt = 0; mt < 4; mt++)
#pragma unroll
            for (int nt = 0; nt < 4; nt++) {
                zlo[mt] += fexp(fminf(acc[mt][nt][0] * 0.125f, 30.f))
                         + fexp(fminf(acc[mt][nt][1] * 0.125f, 30.f));
                zhi[mt] += fexp(fminf(acc[mt][nt][2] * 0.125f, 30.f))
                         + fexp(fminf(acc[mt][nt][3] * 0.125f, 30.f));
            }
    }

    // reduce Z1: qid butterfly, cross-warp smem, broadcast
#pragma unroll
    for (int o = 1; o <= 2; o <<= 1)
#pragma unroll
        for (int mt = 0; mt < 4; mt++) {
            zlo[mt] += __shfl_xor_sync(0xffffffffu, zlo[mt], o);
            zhi[mt] += __shfl_xor_sync(0xffffffffu, zhi[mt], o);
        }
    if (qid == 0) {
#pragma unroll
        for (int mt = 0; mt < 4; mt++) {
            sz[widn][warp_m + mt * 16 + grp]     = zlo[mt];
            sz[widn][warp_m + mt * 16 + grp + 8] = zhi[mt];
        }
    }
    __syncthreads();
    if (tid < 128)
        zbuf[tid] = (sz[0][tid] + sz[1][tid]) + (sz[2][tid] + sz[3][tid]);
    __syncthreads();

    float iZlo[4], iZhi[4];
#pragma unroll
    for (int mt = 0; mt < 4; mt++) {
        iZlo[mt] = 1.0f / zbuf[warp_m + mt * 16 + grp];
        iZhi[mt] = 1.0f / zbuf[warp_m + mt * 16 + grp + 8];
    }

    // ======================= PASS 2: transform + PV =========================
    const int rpv1 = wid * 16 + grp;       // PV-layout rows for this warp
    const int rpv2 = rpv1 + 8;
    float accPV[8][4];
#pragma unroll
    for (int nt = 0; nt < 8; nt++)
#pragma unroll
        for (int r = 0; r < 4; r++) accPV[nt][r] = 0.f;
    float z2lo[4] = {0.f,0.f,0.f,0.f}, z2hi[4] = {0.f,0.f,0.f,0.f};

    for (int n0 = 0; n0 < SS; n0 += 128) {
        __syncthreads();
#pragma unroll
        for (int t = 0; t < 8; t++) {
            int idx = tid + t * 256;
            int row = idx >> 4;
            int c4  = idx & 15;
            float4 vk = *(const float4*)(g_K + (size_t)(b*SS + n0 + row) * DD + h*HW + c4*4);
            *(uint4*)(Ks + row * QST + c4 * 4) =
                make_uint4(f2tf32(vk.x), f2tf32(vk.y), f2tf32(vk.z), f2tf32(vk.w));
            float4 vv = *(const float4*)(g_V + (size_t)(b*SS + n0 + row) * DD + h*HW + c4*4);
            *(uint4*)(Vs + row * VST + c4 * 4) =
                make_uint4(f2tf32(vv.x), f2tf32(vv.y), f2tf32(vv.z), f2tf32(vv.w));
        }
        __syncthreads();

        // recompute s tile
        float acc[4][4][4];
#pragma unroll
        for (int mt = 0; mt < 4; mt++)
#pragma unroll
            for (int nt = 0; nt < 4; nt++)
#pragma unroll
                for (int r = 0; r < 4; r++) acc[mt][nt][r] = 0.f;

#pragma unroll
        for (int ks = 0; ks < 8; ks++) {
            const int kk = ks * 8;
            uint32_t af[4][4], bf[4][2];
#pragma unroll
            for (int mt = 0; mt < 4; mt++) {
                const uint32_t* ap = Qs + (warp_m + mt * 16 + grp) * QST + kk + qid;
                af[mt][0] = ap[0];
                af[mt][1] = ap[8 * QST];
                af[mt][2] = ap[4];
                af[mt][3] = ap[8 * QST + 4];
            }
#pragma unroll
            for (int nt = 0; nt < 4; nt++) {
                const uint32_t* bp = Ks + (warp_n + nt * 8 + grp) * QST + kk + qid;
                bf[nt][0] = bp[0];
                bf[nt][1] = bp[4];
            }
#pragma unroll
            for (int mt = 0; mt < 4; mt++)
#pragma unroll
                for (int nt = 0; nt < 4; nt++)
                    mma_tf32(acc[mt][nt], af[mt][0], af[mt][1], af[mt][2], af[mt][3],
                             bf[nt][0], bf[nt][1]);
        }

        // transform t = exp(e * invZ1), accumulate Z2, store Ts (tf32)
#pragma unroll
        for (int mt = 0; mt < 4; mt++) {
            int r1 = warp_m + mt * 16 + grp;
            int r2 = r1 + 8;
#pragma unroll
            for (int nt = 0; nt < 4; nt++) {
                int col = warp_n + nt * 8 + 2 * qid;
                float e0 = fexp(fminf(acc[mt][nt][0] * 0.125f, 30.f));
                float e1 = fexp(fminf(acc[mt][nt][1] * 0.125f, 30.f));
                float e2 = fexp(fminf(acc[mt][nt][2] * 0.125f, 30.f));
                float e3 = fexp(fminf(acc[mt][nt][3] * 0.125f, 30.f));
                float t0 = fexp(e0 * iZlo[mt]);
                float t1 = fexp(e1 * iZlo[mt]);
                float t2 = fexp(e2 * iZhi[mt]);
                float t3 = fexp(e3 * iZhi[mt]);
                z2lo[mt] += t0 + t1;
                z2hi[mt] += t2 + t3;
                *(uint2*)(Ts + r1 * TST + col) = make_uint2(f2tf32(t0), f2tf32(t1));
                *(uint2*)(Ts + r2 * TST + col) = make_uint2(f2tf32(t2), f2tf32(t3));
            }
        }
        __syncthreads();

        // PV: accPV += Ts @ Vs   (all-m warp layout, 16 k-steps)
#pragma unroll
        for (int ks = 0; ks < 16; ks++) {
            const int kk = ks * 8;
            const uint32_t* ap1 = Ts + rpv1 * TST + kk + qid;
            const uint32_t* ap2 = Ts + rpv2 * TST + kk + qid;
            uint32_t a0 = ap1[0], a1 = ap2[0], a2 = ap1[4], a3 = ap2[4];
#pragma unroll
            for (int nt = 0; nt < 8; nt++) {
                const uint32_t* bp = Vs + (kk + qid) * VST + nt * 8 + grp;
                mma_tf32(accPV[nt], a0, a1, a2, a3, bp[0], bp[4 * VST]);
            }
        }
    }

    // reduce Z2 (score layout) -> smem -> PV rows
#pragma unroll
    for (int o = 1; o <= 2; o <<= 1)
#pragma unroll
        for (int mt = 0; mt < 4; mt++) {
            z2lo[mt] += __shfl_xor_sync(0xffffffffu, z2lo[mt], o);
            z2hi[mt] += __shfl_xor_sync(0xffffffffu, z2hi[mt], o);
        }
    __syncthreads();
    if (qid == 0) {
#pragma unroll
        for (int mt = 0; mt < 4; mt++) {
            sz[widn][warp_m + mt * 16 + grp]     = z2lo[mt];
            sz[widn][warp_m + mt * 16 + grp + 8] = z2hi[mt];
        }
    }
    __syncthreads();
    if (tid < 128)
        zbuf[tid] = (sz[0][tid] + sz[1][tid]) + (sz[2][tid] + sz[3][tid]);
    __syncthreads();

    const float rlo = 1.0f / zbuf[rpv1];
    const float rhi = 1.0f / zbuf[rpv2];

#pragma unroll
    for (int nt = 0; nt < 8; nt++) {
        int col = h * HW + nt * 8 + 2 * qid;
        *(float2*)(out + (size_t)(b*SS + q0 + rpv1) * DD + col) =
            make_float2(accPV[nt][0] * rlo, accPV[nt][1] * rlo);
        *(float2*)(out + (size_t)(b*SS + q0 + rpv2) * DD + col) =
            make_float2(accPV[nt][2] * rhi, accPV[nt][3] * rhi);
    }
}

// ---------------- launch -----------------------------------------------------
extern "C" void kernel_launch(void* const* d_in, const int* in_sizes, int n_in,
                              void* d_out, int out_size) {
    const float* x  = (const float*)d_in[0];
    const float* Wq = (const float*)d_in[1];
    const float* bq = (const float*)d_in[2];
    const float* Wk = (const float*)d_in[3];
    const float* bk = (const float*)d_in[4];
    const float* Wv = (const float*)d_in[5];
    const float* bv = (const float*)d_in[6];
    float* out = (float*)d_out;

    dim3 gproj(DD / 128, MM / 128, 3);          // (8, 32, 3)
    gemm_tf32<<<gproj, 256>>>(x, Wq, bq, Wk, bk, Wv, bv);

    const int smem_attn =
        (2 * 128 * QST + 128 * TST + 128 * VST) * sizeof(uint32_t); // 174080
    cudaFuncSetAttribute(attn_fused_mma,
                         cudaFuncAttributeMaxDynamicSharedMemorySize, smem_attn);
    dim3 ga(SS / 128, BB * HH);                 // (16, 32)
    attn_fused_mma<<<ga, 256, smem_attn>>>(out);
}

// round 9
// speedup vs baseline: 1.2886x; 1.2886x over previous
#include <cuda_runtime.h>
#include <cuda_fp16.h>
#include <cstdint>
#include <math.h>

#define BB 2
#define SS 2048
#define DD 1024
#define HH 16
#define HW 64
#define MM (BB*SS)   // 4096

// ---------------- scratch (no cudaMalloc allowed) ---------------------------
__device__ float  g_Q[(size_t)MM * DD];                 // 16 MB
__device__ float  g_K[(size_t)MM * DD];                 // 16 MB
__device__ float  g_V[(size_t)MM * DD];                 // 16 MB
__device__ __half g_S[(size_t)BB * HH * SS * SS];       // 256 MB (e^s, fp16)
__device__ float  g_Z[(size_t)BB * HH * SS];            // row sums Z1

// ---------------- PTX helpers (non-arch-specific only) ----------------------
__device__ __forceinline__ uint32_t f2tf32(float x) {
    uint32_t u; asm("cvt.rna.tf32.f32 %0, %1;" : "=r"(u) : "f"(x)); return u;
}
__device__ __forceinline__ void mma_tf32(float c[4],
                                         uint32_t a0, uint32_t a1, uint32_t a2, uint32_t a3,
                                         uint32_t b0, uint32_t b1) {
    asm volatile(
        "mma.sync.aligned.m16n8k8.row.col.f32.tf32.tf32.f32 "
        "{%0,%1,%2,%3}, {%4,%5,%6,%7}, {%8,%9}, {%0,%1,%2,%3};"
        : "+f"(c[0]), "+f"(c[1]), "+f"(c[2]), "+f"(c[3])
        : "r"(a0), "r"(a1), "r"(a2), "r"(a3), "r"(b0), "r"(b1));
}
__device__ __forceinline__ uint32_t smem_u32(const void* p) {
    uint32_t a;
    asm("{ .reg .u64 t; cvta.to.shared.u64 t, %1; cvt.u32.u64 %0, t; }"
        : "=r"(a) : "l"(p));
    return a;
}
__device__ __forceinline__ void cp_async16(uint32_t s, const void* g) {
    asm volatile("cp.async.cg.shared.global [%0], [%1], 16;" :: "r"(s), "l"(g));
}
__device__ __forceinline__ void cp_commit() {
    asm volatile("cp.async.commit_group;" ::: "memory");
}
__device__ __forceinline__ void cp_wait1() {
    asm volatile("cp.async.wait_group 1;" ::: "memory");
}

// ---------------- fast exp on the FFMA pipe ---------------------------------
__device__ __forceinline__ float fexp(float x) {
    float y = fmaxf(x * 1.4426950408889634f, -126.0f);
    float n = rintf(y);
    float f = y - n;
    float p =              1.5403530393381606e-4f;
    p = fmaf(p, f, 1.3333558146428443e-3f);
    p = fmaf(p, f, 9.6181291076284772e-3f);
    p = fmaf(p, f, 5.5504108664821580e-2f);
    p = fmaf(p, f, 2.4022650695910071e-1f);
    p = fmaf(p, f, 6.9314718055994531e-1f);
    p = fmaf(p, f, 1.0f);
    int e = (((int)n) + 127) << 23;
    return p * __int_as_float(e);
}

// ============================================================================
// K1: tf32 GEMM, cp.async double-buffered raw tiles, cvt at fragment load.
// C = X @ W^T + b. CTA 128x128, BK=32, 8 warps (2m x 4n). z picks Q/K/V.
// ============================================================================
#define GST 36

__global__ void __launch_bounds__(256, 2)
gemm_tf32_cp(const float* __restrict__ A,
             const float* __restrict__ Wq, const float* __restrict__ bq,
             const float* __restrict__ Wk, const float* __restrict__ bk,
             const float* __restrict__ Wv, const float* __restrict__ bv) {
    const int which = blockIdx.z;
    const float* W    = (which == 0) ? Wq : (which == 1) ? Wk : Wv;
    const float* bias = (which == 0) ? bq : (which == 1) ? bk : bv;
    float* C          = (which == 0) ? g_Q : (which == 1) ? g_K : g_V;

    extern __shared__ float dynf[];
    float* sAr = dynf;                     // [2][128*GST]
    float* sBr = dynf + 2 * 128 * GST;     // [2][128*GST]
    const uint32_t aBase = smem_u32(sAr);
    const uint32_t bBase = smem_u32(sBr);

    const int tid  = threadIdx.x;
    const int wid  = tid >> 5;
    const int lane = tid & 31;
    const int grp  = lane >> 2;
    const int qid  = lane & 3;
    const int m0 = blockIdx.y * 128;
    const int n0 = blockIdx.x * 128;
    const int warp_m = (wid & 1) * 64;
    const int warp_n = (wid >> 1) * 32;

    // prologue: issue tile 0
#pragma unroll
    for (int t = 0; t < 4; t++) {
        int idx = tid + t * 256;
        int row = idx >> 3;
        int c4  = idx & 7;
        cp_async16(aBase + (uint32_t)(row * GST + c4 * 4) * 4,
                   A + (size_t)(m0 + row) * DD + c4 * 4);
        cp_async16(bBase + (uint32_t)(row * GST + c4 * 4) * 4,
                   W + (size_t)(n0 + row) * DD + c4 * 4);
    }
    cp_commit();

    float acc[4][4][4];
#pragma unroll
    for (int mt = 0; mt < 4; mt++)
#pragma unroll
        for (int nt = 0; nt < 4; nt++)
#pragma unroll
            for (int r = 0; r < 4; r++) acc[mt][nt][r] = 0.f;

    for (int kc = 0; kc < 32; kc++) {
        const int buf = kc & 1;
        if (kc + 1 < 32) {
            const int k1 = (kc + 1) * 32;
#pragma unroll
            for (int t = 0; t < 4; t++) {
                int idx = tid + t * 256;
                int row = idx >> 3;
                int c4  = idx & 7;
                cp_async16(aBase + (uint32_t)((buf^1) * 128 * GST + row * GST + c4 * 4) * 4,
                           A + (size_t)(m0 + row) * DD + k1 + c4 * 4);
                cp_async16(bBase + (uint32_t)((buf^1) * 128 * GST + row * GST + c4 * 4) * 4,
                           W + (size_t)(n0 + row) * DD + k1 + c4 * 4);
            }
        }
        cp_commit();
        cp_wait1();
        __syncthreads();

        const float* Ab = sAr + buf * 128 * GST;
        const float* Bb = sBr + buf * 128 * GST;
#pragma unroll
        for (int ks = 0; ks < 4; ks++) {
            const int kk = ks * 8;
            uint32_t af[4][4], bf[4][2];
#pragma unroll
            for (int mt = 0; mt < 4; mt++) {
                const float* ap = Ab + (warp_m + mt * 16 + grp) * GST + kk + qid;
                af[mt][0] = f2tf32(ap[0]);
                af[mt][1] = f2tf32(ap[8 * GST]);
                af[mt][2] = f2tf32(ap[4]);
                af[mt][3] = f2tf32(ap[8 * GST + 4]);
            }
#pragma unroll
            for (int nt = 0; nt < 4; nt++) {
                const float* bp = Bb + (warp_n + nt * 8 + grp) * GST + kk + qid;
                bf[nt][0] = f2tf32(bp[0]);
                bf[nt][1] = f2tf32(bp[4]);
            }
#pragma unroll
            for (int mt = 0; mt < 4; mt++)
#pragma unroll
                for (int nt = 0; nt < 4; nt++)
                    mma_tf32(acc[mt][nt], af[mt][0], af[mt][1], af[mt][2], af[mt][3],
                             bf[nt][0], bf[nt][1]);
        }
        __syncthreads();
    }

#pragma unroll
    for (int mt = 0; mt < 4; mt++) {
#pragma unroll
        for (int nt = 0; nt < 4; nt++) {
            int col = n0 + warp_n + nt * 8 + 2 * qid;
            float bx = bias[col], by = bias[col + 1];
            int r0 = m0 + warp_m + mt * 16 + grp;
            *(float2*)(C + (size_t)r0 * DD + col) =
                make_float2(acc[mt][nt][0] + bx, acc[mt][nt][1] + by);
            *(float2*)(C + (size_t)(r0 + 8) * DD + col) =
                make_float2(acc[mt][nt][2] + bx, acc[mt][nt][3] + by);
        }
    }
}

// ============================================================================
// K2: scores — e = exp(s/8) (fp16) -> g_S, Z1 -> g_Z.
// cp.async double-buffered raw K; Q tf32 resident; 8 warps (2m x 4n).
// ============================================================================
#define QST 68

__global__ void __launch_bounds__(256, 2)
attn_scores_cp() {
    extern __shared__ uint32_t dyn[];
    uint32_t* Qs = dyn;                        // [128][QST] tf32
    float*    Kr = (float*)(dyn + 128 * QST);  // [2][128][QST] raw
    __shared__ float sz[4][128];
    __shared__ float zbuf[128];

    const int bh = blockIdx.y;
    const int b  = bh >> 4, h = bh & 15;
    const int q0 = blockIdx.x * 128;
    const int tid  = threadIdx.x;
    const int wid  = tid >> 5;
    const int lane = tid & 31;
    const int grp  = lane >> 2;
    const int qid  = lane & 3;
    const int widm = wid & 1, widn = wid >> 1;
    const int warp_m = widm * 64, warp_n = widn * 32;
    __half* Sm = g_S + (size_t)bh * SS * SS;
    const uint32_t krBase = smem_u32(Kr);

    // start K tile 0 DMA first, overlap with Q convert
#pragma unroll
    for (int t = 0; t < 8; t++) {
        int idx = tid + t * 256;
        int row = idx >> 4;
        int c4  = idx & 15;
        cp_async16(krBase + (uint32_t)(row * QST + c4 * 4) * 4,
                   g_K + (size_t)(b*SS + row) * DD + h*HW + c4*4);
    }
    cp_commit();

    // Q tile -> tf32 smem
#pragma unroll
    for (int t = 0; t < 8; t++) {
        int idx = tid + t * 256;
        int row = idx >> 4;
        int c4  = idx & 15;
        float4 v = *(const float4*)(g_Q + (size_t)(b*SS + q0 + row) * DD + h*HW + c4*4);
        *(uint4*)(Qs + row * QST + c4 * 4) =
            make_uint4(f2tf32(v.x), f2tf32(v.y), f2tf32(v.z), f2tf32(v.w));
    }

    float zlo[4] = {0.f,0.f,0.f,0.f}, zhi[4] = {0.f,0.f,0.f,0.f};

    for (int it = 0; it < 16; it++) {
        const int buf = it & 1;
        if (it + 1 < 16) {
            const int n1 = (it + 1) * 128;
#pragma unroll
            for (int t = 0; t < 8; t++) {
                int idx = tid + t * 256;
                int row = idx >> 4;
                int c4  = idx & 15;
                cp_async16(krBase + (uint32_t)((buf^1) * 128 * QST + row * QST + c4 * 4) * 4,
                           g_K + (size_t)(b*SS + n1 + row) * DD + h*HW + c4*4);
            }
        }
        cp_commit();
        cp_wait1();
        __syncthreads();

        const float* Kb = Kr + buf * 128 * QST;
        float acc[4][4][4];
#pragma unroll
        for (int mt = 0; mt < 4; mt++)
#pragma unroll
            for (int nt = 0; nt < 4; nt++)
#pragma unroll
                for (int r = 0; r < 4; r++) acc[mt][nt][r] = 0.f;

#pragma unroll
        for (int ks = 0; ks < 8; ks++) {
            const int kk = ks * 8;
            uint32_t af[4][4], bf[4][2];
#pragma unroll
            for (int mt = 0; mt < 4; mt++) {
                const uint32_t* ap = Qs + (warp_m + mt * 16 + grp) * QST + kk + qid;
                af[mt][0] = ap[0];
                af[mt][1] = ap[8 * QST];
                af[mt][2] = ap[4];
                af[mt][3] = ap[8 * QST + 4];
            }
#pragma unroll
            for (int nt = 0; nt < 4; nt++) {
                const float* bp = Kb + (warp_n + nt * 8 + grp) * QST + kk + qid;
                bf[nt][0] = f2tf32(bp[0]);
                bf[nt][1] = f2tf32(bp[4]);
            }
#pragma unroll
            for (int mt = 0; mt < 4; mt++)
#pragma unroll
                for (int nt = 0; nt < 4; nt++)
                    mma_tf32(acc[mt][nt], af[mt][0], af[mt][1], af[mt][2], af[mt][3],
                             bf[nt][0], bf[nt][1]);
        }

        const int n0 = it * 128;
#pragma unroll
        for (int mt = 0; mt < 4; mt++) {
            int r1 = warp_m + mt * 16 + grp;
            int r2 = r1 + 8;
#pragma unroll
            for (int nt = 0; nt < 4; nt++) {
                int col = n0 + warp_n + nt * 8 + 2 * qid;
                float e0 = fexp(fminf(acc[mt][nt][0] * 0.125f, 10.f));
                float e1 = fexp(fminf(acc[mt][nt][1] * 0.125f, 10.f));
                float e2 = fexp(fminf(acc[mt][nt][2] * 0.125f, 10.f));
                float e3 = fexp(fminf(acc[mt][nt][3] * 0.125f, 10.f));
                __half2 hA = __floats2half2_rn(e0, e1);
                __half2 hB = __floats2half2_rn(e2, e3);
                // accumulate Z1 from the rounded values pass 2 will read
                zlo[mt] += __low2float(hA) + __high2float(hA);
                zhi[mt] += __low2float(hB) + __high2float(hB);
                *(__half2*)(Sm + (size_t)(q0 + r1) * SS + col) = hA;
                *(__half2*)(Sm + (size_t)(q0 + r2) * SS + col) = hB;
            }
        }
        __syncthreads();
    }

    // reduce Z1: qid butterfly, then across the 4 n-warps via smem
#pragma unroll
    for (int o = 1; o <= 2; o <<= 1)
#pragma unroll
        for (int mt = 0; mt < 4; mt++) {
            zlo[mt] += __shfl_xor_sync(0xffffffffu, zlo[mt], o);
            zhi[mt] += __shfl_xor_sync(0xffffffffu, zhi[mt], o);
        }
    if (qid == 0) {
#pragma unroll
        for (int mt = 0; mt < 4; mt++) {
            sz[widn][warp_m + mt * 16 + grp]     = zlo[mt];
            sz[widn][warp_m + mt * 16 + grp + 8] = zhi[mt];
        }
    }
    __syncthreads();
    if (tid < 128) {
        float z = (sz[0][tid] + sz[1][tid]) + (sz[2][tid] + sz[3][tid]);
        g_Z[(size_t)bh * SS + q0 + tid] = z;
    }
}

// ============================================================================
// K3: PV — t = exp(e/Z1); out = (t @ V)/Z2.
// cp.async double-buffered E (fp16) + V (raw fp32). 8 warps all-m (16 q each).
// ============================================================================
#define EST 72   // halves per row
#define VST 72   // floats per row

__global__ void __launch_bounds__(256, 2)
attn_pv_cp(float* __restrict__ out) {
    extern __shared__ uint32_t dyn2[];
    __half* Eh = (__half*)dyn2;                   // [2][128][EST]
    float*  Vr = (float*)(dyn2 + (2*128*EST)/2);  // [2][64][VST]
    const uint32_t ehBase = smem_u32(Eh);
    const uint32_t vrBase = smem_u32(Vr);

    const int bh = blockIdx.y;
    const int b  = bh >> 4, h = bh & 15;
    const int q0 = blockIdx.x * 128;
    const int tid  = threadIdx.x;
    const int wid  = tid >> 5;
    const int lane = tid & 31;
    const int grp  = lane >> 2;
    const int qid  = lane & 3;
    const __half* Sm = g_S + (size_t)bh * SS * SS;

    const int rA = wid * 16 + grp;       // this warp's two q rows
    const int rB = rA + 8;
    const float invZa = 1.0f / g_Z[(size_t)bh * SS + q0 + rA];
    const float invZb = 1.0f / g_Z[(size_t)bh * SS + q0 + rB];

    // prologue: issue tile 0 (E rows 128 x 64 halves; V rows 64 x 64 floats)
#pragma unroll
    for (int t = 0; t < 4; t++) {
        int idx = tid + t * 256;
        int er = idx >> 3, ec = idx & 7;
        cp_async16(ehBase + (uint32_t)(er * EST + ec * 8) * 2,
                   Sm + (size_t)(q0 + er) * SS + ec * 8);
        int vr = idx >> 4, vc = idx & 15;
        cp_async16(vrBase + (uint32_t)(vr * VST + vc * 4) * 4,
                   g_V + (size_t)(b*SS + vr) * DD + h*HW + vc*4);
    }
    cp_commit();

    float accPV[8][4];
#pragma unroll
    for (int nt = 0; nt < 8; nt++)
#pragma unroll
        for (int r = 0; r < 4; r++) accPV[nt][r] = 0.f;
    float z2a = 0.f, z2b = 0.f;

    for (int it = 0; it < 32; it++) {
        const int buf = it & 1;
        if (it + 1 < 32) {
            const int k1 = (it + 1) * 64;
#pragma unroll
            for (int t = 0; t < 4; t++) {
                int idx = tid + t * 256;
                int er = idx >> 3, ec = idx & 7;
                cp_async16(ehBase + (uint32_t)((buf^1) * 128 * EST + er * EST + ec * 8) * 2,
                           Sm + (size_t)(q0 + er) * SS + k1 + ec * 8);
                int vr = idx >> 4, vc = idx & 15;
                cp_async16(vrBase + (uint32_t)((buf^1) * 64 * VST + vr * VST + vc * 4) * 4,
                           g_V + (size_t)(b*SS + k1 + vr) * DD + h*HW + vc*4);
            }
        }
        cp_commit();
        cp_wait1();
        __syncthreads();

        const __half* Eb = Eh + buf * 128 * EST;
        const float*  Vb = Vr + buf * 64 * VST;

#pragma unroll
        for (int ks = 0; ks < 8; ks++) {
            const int kk = ks * 8;
            float e0 = __half2float(Eb[rA * EST + kk + qid]);
            float e1 = __half2float(Eb[rB * EST + kk + qid]);
            float e2 = __half2float(Eb[rA * EST + kk + qid + 4]);
            float e3 = __half2float(Eb[rB * EST + kk + qid + 4]);
            float t0 = fexp(e0 * invZa);
            float t1 = fexp(e1 * invZb);
            float t2 = fexp(e2 * invZa);
            float t3 = fexp(e3 * invZb);
            z2a += t0 + t2;
            z2b += t1 + t3;
            uint32_t a0 = f2tf32(t0), a1 = f2tf32(t1), a2 = f2tf32(t2), a3 = f2tf32(t3);
#pragma unroll
            for (int nt = 0; nt < 8; nt++) {
                const float* bp = Vb + (kk + qid) * VST + nt * 8 + grp;
                mma_tf32(accPV[nt], a0, a1, a2, a3, f2tf32(bp[0]), f2tf32(bp[4 * VST]));
            }
        }
        __syncthreads();
    }

    // Z2: butterfly over the 4 qid lanes (row owned by exactly this warp)
#pragma unroll
    for (int o = 1; o <= 2; o <<= 1) {
        z2a += __shfl_xor_sync(0xffffffffu, z2a, o);
        z2b += __shfl_xor_sync(0xffffffffu, z2b, o);
    }
    const float ra = 1.0f / z2a;
    const float rb = 1.0f / z2b;

#pragma unroll
    for (int nt = 0; nt < 8; nt++) {
        int col = h * HW + nt * 8 + 2 * qid;
        *(float2*)(out + (size_t)(b*SS + q0 + rA) * DD + col) =
            make_float2(accPV[nt][0] * ra, accPV[nt][1] * ra);
        *(float2*)(out + (size_t)(b*SS + q0 + rB) * DD + col) =
            make_float2(accPV[nt][2] * rb, accPV[nt][3] * rb);
    }
}

// ---------------- launch -----------------------------------------------------
extern "C" void kernel_launch(void* const* d_in, const int* in_sizes, int n_in,
                              void* d_out, int out_size) {
    const float* x  = (const float*)d_in[0];
    const float* Wq = (const float*)d_in[1];
    const float* bq = (const float*)d_in[2];
    const float* Wk = (const float*)d_in[3];
    const float* bk = (const float*)d_in[4];
    const float* Wv = (const float*)d_in[5];
    const float* bv = (const float*)d_in[6];
    float* out = (float*)d_out;

    const int smem_gemm = 4 * 128 * GST * sizeof(float);                 // 73728
    const int smem_sc   = (128 * QST + 2 * 128 * QST) * sizeof(float);   // 104448
    const int smem_pv   = 2 * 128 * EST * 2 + 2 * 64 * VST * 4;          // 73728
    cudaFuncSetAttribute(gemm_tf32_cp,
                         cudaFuncAttributeMaxDynamicSharedMemorySize, smem_gemm);
    cudaFuncSetAttribute(attn_scores_cp,
                         cudaFuncAttributeMaxDynamicSharedMemorySize, smem_sc);
    cudaFuncSetAttribute(attn_pv_cp,
                         cudaFuncAttributeMaxDynamicSharedMemorySize, smem_pv);

    dim3 gproj(DD / 128, MM / 128, 3);          // (8, 32, 3)
    gemm_tf32_cp<<<gproj, 256, smem_gemm>>>(x, Wq, bq, Wk, bk, Wv, bv);

    dim3 gs(SS / 128, BB * HH);                 // (16, 32)
    attn_scores_cp<<<gs, 256, smem_sc>>>();
    attn_pv_cp<<<gs, 256, smem_pv>>>(out);
}

// round 10
// speedup vs baseline: 2.0512x; 1.5918x over previous
#include <cuda_runtime.h>
#include <cuda_fp16.h>
#include <cstdint>
#include <math.h>

#define BB 2
#define SS 2048
#define DD 1024
#define HH 16
#define HW 64
#define MM (BB*SS)   // 4096

// ---------------- scratch (no cudaMalloc allowed) ---------------------------
__device__ __half g_xh[(size_t)MM * DD];                // 8 MB  x in fp16
__device__ __half g_Wh[3][(size_t)DD * DD];             // 6 MB  Wq/Wk/Wv fp16
__device__ __half g_Qh[(size_t)MM * DD];                // 8 MB
__device__ __half g_Kh[(size_t)MM * DD];                // 8 MB
__device__ __half g_Vt[(size_t)MM * DD];                // 8 MB  V transposed per head: [bh][w][s]
__device__ __half g_S [(size_t)BB * HH * SS * SS];      // 256 MB (e^s fp16)
__device__ float  g_Z [(size_t)BB * HH * SS];           // Z1

// ---------------- PTX helpers (non-arch-specific only) ----------------------
__device__ __forceinline__ void mma_f16(float c[4],
                                        uint32_t a0, uint32_t a1, uint32_t a2, uint32_t a3,
                                        uint32_t b0, uint32_t b1) {
    asm volatile(
        "mma.sync.aligned.m16n8k16.row.col.f32.f16.f16.f32 "
        "{%0,%1,%2,%3}, {%4,%5,%6,%7}, {%8,%9}, {%0,%1,%2,%3};"
        : "+f"(c[0]), "+f"(c[1]), "+f"(c[2]), "+f"(c[3])
        : "r"(a0), "r"(a1), "r"(a2), "r"(a3), "r"(b0), "r"(b1));
}
__device__ __forceinline__ uint32_t smem_u32(const void* p) {
    uint32_t a;
    asm("{ .reg .u64 t; cvta.to.shared.u64 t, %1; cvt.u32.u64 %0, t; }"
        : "=r"(a) : "l"(p));
    return a;
}
__device__ __forceinline__ void cp_async16(uint32_t s, const void* g) {
    asm volatile("cp.async.cg.shared.global [%0], [%1], 16;" :: "r"(s), "l"(g));
}
__device__ __forceinline__ void cp_commit() {
    asm volatile("cp.async.commit_group;" ::: "memory");
}
__device__ __forceinline__ void cp_wait1() {
    asm volatile("cp.async.wait_group 1;" ::: "memory");
}

// ---------------- fast exp on the FFMA pipe ---------------------------------
__device__ __forceinline__ float fexp(float x) {
    float y = fmaxf(x * 1.4426950408889634f, -126.0f);
    float n = rintf(y);
    float f = y - n;
    float p =              1.5403530393381606e-4f;
    p = fmaf(p, f, 1.3333558146428443e-3f);
    p = fmaf(p, f, 9.6181291076284772e-3f);
    p = fmaf(p, f, 5.5504108664821580e-2f);
    p = fmaf(p, f, 2.4022650695910071e-1f);
    p = fmaf(p, f, 6.9314718055994531e-1f);
    p = fmaf(p, f, 1.0f);
    int e = (((int)n) + 127) << 23;
    return p * __int_as_float(e);
}

// ============================================================================
// K0: fp32 -> fp16 convert for x and the three W matrices
// grid (512, 7): y<4 -> x chunk y (1M floats each); y=4,5,6 -> Wq/Wk/Wv
// ============================================================================
__global__ void __launch_bounds__(256)
to_half_k(const float* __restrict__ x,  const float* __restrict__ Wq,
          const float* __restrict__ Wk, const float* __restrict__ Wv) {
    const int seg = blockIdx.y;
    const size_t idx = ((size_t)blockIdx.x * 256 + threadIdx.x) * 8;
    const float* src;
    __half* dst;
    if (seg < 4) { src = x + (size_t)seg * 1048576; dst = g_xh + (size_t)seg * 1048576; }
    else if (seg == 4) { src = Wq; dst = g_Wh[0]; }
    else if (seg == 5) { src = Wk; dst = g_Wh[1]; }
    else               { src = Wv; dst = g_Wh[2]; }
    float4 a = *(const float4*)(src + idx);
    float4 b = *(const float4*)(src + idx + 4);
    __half2 h0 = __floats2half2_rn(a.x, a.y);
    __half2 h1 = __floats2half2_rn(a.z, a.w);
    __half2 h2 = __floats2half2_rn(b.x, b.y);
    __half2 h3 = __floats2half2_rn(b.z, b.w);
    uint4 o;
    o.x = *(uint32_t*)&h0; o.y = *(uint32_t*)&h1;
    o.z = *(uint32_t*)&h2; o.w = *(uint32_t*)&h3;
    *(uint4*)(dst + idx) = o;
}

// ============================================================================
// K1: fp16 m16n8k16 GEMM  C = X @ W^T + b. CTA 128x128, BK=64, 8 warps (2m x 4n).
// Q,K -> row layout fp16. V -> per-head transposed layout g_Vt[bh*64+w][s].
// ============================================================================
#define HST 72   // tile row stride in halves (word stride 36)

__global__ void __launch_bounds__(256, 2)
gemm_h(const float* __restrict__ bq, const float* __restrict__ bk,
       const float* __restrict__ bv) {
    const int which = blockIdx.z;
    const __half* W    = g_Wh[which];
    const float* bias  = (which == 0) ? bq : (which == 1) ? bk : bv;

    extern __shared__ __half hsm[];
    __half* At = hsm;                  // [2][128][HST]
    __half* Bt = hsm + 2 * 128 * HST;  // [2][128][HST]
    const uint32_t aBase = smem_u32(At);
    const uint32_t bBase = smem_u32(Bt);

    const int tid  = threadIdx.x;
    const int wid  = tid >> 5;
    const int lane = tid & 31;
    const int grp  = lane >> 2;
    const int qid  = lane & 3;
    const int m0 = blockIdx.y * 128;
    const int n0 = blockIdx.x * 128;
    const int warp_m = (wid & 1) * 64;
    const int warp_n = (wid >> 1) * 32;

    // prologue: tile 0 (each thread copies 4 16B chunks per operand)
#pragma unroll
    for (int t = 0; t < 4; t++) {
        int idx = tid + t * 256;
        int row = idx >> 3;
        int c8  = idx & 7;
        cp_async16(aBase + (uint32_t)(row * HST + c8 * 8) * 2,
                   g_xh + (size_t)(m0 + row) * DD + c8 * 8);
        cp_async16(bBase + (uint32_t)(row * HST + c8 * 8) * 2,
                   W + (size_t)(n0 + row) * DD + c8 * 8);
    }
    cp_commit();

    float acc[4][4][4];
#pragma unroll
    for (int mt = 0; mt < 4; mt++)
#pragma unroll
        for (int nt = 0; nt < 4; nt++)
#pragma unroll
            for (int r = 0; r < 4; r++) acc[mt][nt][r] = 0.f;

    for (int kc = 0; kc < 16; kc++) {
        const int buf = kc & 1;
        if (kc + 1 < 16) {
            const int k1 = (kc + 1) * 64;
#pragma unroll
            for (int t = 0; t < 4; t++) {
                int idx = tid + t * 256;
                int row = idx >> 3;
                int c8  = idx & 7;
                cp_async16(aBase + (uint32_t)((buf^1) * 128 * HST + row * HST + c8 * 8) * 2,
                           g_xh + (size_t)(m0 + row) * DD + k1 + c8 * 8);
                cp_async16(bBase + (uint32_t)((buf^1) * 128 * HST + row * HST + c8 * 8) * 2,
                           W + (size_t)(n0 + row) * DD + k1 + c8 * 8);
            }
        }
        cp_commit();
        cp_wait1();
        __syncthreads();

        const __half* Ab = At + buf * 128 * HST;
        const __half* Bb = Bt + buf * 128 * HST;
#pragma unroll
        for (int ks = 0; ks < 4; ks++) {
            uint32_t af[4][4], bf[4][2];
#pragma unroll
            for (int mt = 0; mt < 4; mt++) {
                const uint32_t* ap1 = (const uint32_t*)(Ab + (warp_m + mt*16 + grp) * HST) + ks*8 + qid;
                const uint32_t* ap2 = (const uint32_t*)(Ab + (warp_m + mt*16 + grp + 8) * HST) + ks*8 + qid;
                af[mt][0] = ap1[0];
                af[mt][1] = ap2[0];
                af[mt][2] = ap1[4];
                af[mt][3] = ap2[4];
            }
#pragma unroll
            for (int nt = 0; nt < 4; nt++) {
                const uint32_t* bp = (const uint32_t*)(Bb + (warp_n + nt*8 + grp) * HST) + ks*8 + qid;
                bf[nt][0] = bp[0];
                bf[nt][1] = bp[4];
            }
#pragma unroll
            for (int mt = 0; mt < 4; mt++)
#pragma unroll
                for (int nt = 0; nt < 4; nt++)
                    mma_f16(acc[mt][nt], af[mt][0], af[mt][1], af[mt][2], af[mt][3],
                            bf[nt][0], bf[nt][1]);
        }
        __syncthreads();
    }

    // epilogue
    if (which < 2) {
        __half* C = (which == 0) ? g_Qh : g_Kh;
#pragma unroll
        for (int mt = 0; mt < 4; mt++) {
#pragma unroll
            for (int nt = 0; nt < 4; nt++) {
                int col = n0 + warp_n + nt * 8 + 2 * qid;
                float bx = bias[col], by = bias[col + 1];
                int r0 = m0 + warp_m + mt * 16 + grp;
                __half2 o0 = __floats2half2_rn(acc[mt][nt][0] + bx, acc[mt][nt][1] + by);
                __half2 o1 = __floats2half2_rn(acc[mt][nt][2] + bx, acc[mt][nt][3] + by);
                *(__half2*)(C + (size_t)r0 * DD + col) = o0;
                *(__half2*)(C + (size_t)(r0 + 8) * DD + col) = o1;
            }
        }
    } else {
        // V: transposed per-head store g_Vt[((b*16+h)*64 + w) * SS + s]
#pragma unroll
        for (int mt = 0; mt < 4; mt++) {
#pragma unroll
            for (int nt = 0; nt < 4; nt++) {
                int col = n0 + warp_n + nt * 8 + 2 * qid;
                float bx = bias[col], by = bias[col + 1];
                int r0 = m0 + warp_m + mt * 16 + grp;
                int hh = col >> 6, w = col & 63;
                int b1 = r0 >> 11, s1 = r0 & 2047;
                size_t base = ((size_t)(b1 * 16 + hh) * 64);
                g_Vt[(base + w    ) * SS + s1]     = __float2half(acc[mt][nt][0] + bx);
                g_Vt[(base + w + 1) * SS + s1]     = __float2half(acc[mt][nt][1] + by);
                g_Vt[(base + w    ) * SS + s1 + 8] = __float2half(acc[mt][nt][2] + bx);
                g_Vt[(base + w + 1) * SS + s1 + 8] = __float2half(acc[mt][nt][3] + by);
            }
        }
    }
}

// ============================================================================
// K2: scores — e = exp(s/8) (fp16) -> g_S, Z1 -> g_Z.
// fp16 Q resident; cp.async double-buffered fp16 K. 8 warps (2m x 4n).
// ============================================================================
__global__ void __launch_bounds__(256, 2)
attn_scores_h() {
    extern __shared__ __half hsm2[];
    __half* Qs = hsm2;                  // [128][HST]
    __half* Kt = hsm2 + 128 * HST;      // [2][128][HST]
    __shared__ float sz[4][128];
    const uint32_t kBase = smem_u32(Kt);

    const int bh = blockIdx.y;
    const int b  = bh >> 4, h = bh & 15;
    const int q0 = blockIdx.x * 128;
    const int tid  = threadIdx.x;
    const int wid  = tid >> 5;
    const int lane = tid & 31;
    const int grp  = lane >> 2;
    const int qid  = lane & 3;
    const int widm = wid & 1, widn = wid >> 1;
    const int warp_m = widm * 64, warp_n = widn * 32;
    __half* Sm = g_S + (size_t)bh * SS * SS;

    // start K tile 0 DMA
#pragma unroll
    for (int t = 0; t < 4; t++) {
        int idx = tid + t * 256;
        int row = idx >> 3;
        int c8  = idx & 7;
        cp_async16(kBase + (uint32_t)(row * HST + c8 * 8) * 2,
                   g_Kh + (size_t)(b*SS + row) * DD + h*HW + c8*8);
    }
    cp_commit();

    // Q tile resident
#pragma unroll
    for (int t = 0; t < 4; t++) {
        int idx = tid + t * 256;
        int row = idx >> 3;
        int c8  = idx & 7;
        uint4 v = *(const uint4*)(g_Qh + (size_t)(b*SS + q0 + row) * DD + h*HW + c8*8);
        *(uint4*)(Qs + row * HST + c8 * 8) = v;
    }

    float zlo[4] = {0.f,0.f,0.f,0.f}, zhi[4] = {0.f,0.f,0.f,0.f};

    for (int it = 0; it < 16; it++) {
        const int buf = it & 1;
        if (it + 1 < 16) {
            const int n1 = (it + 1) * 128;
#pragma unroll
            for (int t = 0; t < 4; t++) {
                int idx = tid + t * 256;
                int row = idx >> 3;
                int c8  = idx & 7;
                cp_async16(kBase + (uint32_t)((buf^1) * 128 * HST + row * HST + c8 * 8) * 2,
                           g_Kh + (size_t)(b*SS + n1 + row) * DD + h*HW + c8*8);
            }
        }
        cp_commit();
        cp_wait1();
        __syncthreads();

        const __half* Kb = Kt + buf * 128 * HST;
        float acc[4][4][4];
#pragma unroll
        for (int mt = 0; mt < 4; mt++)
#pragma unroll
            for (int nt = 0; nt < 4; nt++)
#pragma unroll
                for (int r = 0; r < 4; r++) acc[mt][nt][r] = 0.f;

#pragma unroll
        for (int ks = 0; ks < 4; ks++) {
            uint32_t af[4][4], bf[4][2];
#pragma unroll
            for (int mt = 0; mt < 4; mt++) {
                const uint32_t* ap1 = (const uint32_t*)(Qs + (warp_m + mt*16 + grp) * HST) + ks*8 + qid;
                const uint32_t* ap2 = (const uint32_t*)(Qs + (warp_m + mt*16 + grp + 8) * HST) + ks*8 + qid;
                af[mt][0] = ap1[0];
                af[mt][1] = ap2[0];
                af[mt][2] = ap1[4];
                af[mt][3] = ap2[4];
            }
#pragma unroll
            for (int nt = 0; nt < 4; nt++) {
                const uint32_t* bp = (const uint32_t*)(Kb + (warp_n + nt*8 + grp) * HST) + ks*8 + qid;
                bf[nt][0] = bp[0];
                bf[nt][1] = bp[4];
            }
#pragma unroll
            for (int mt = 0; mt < 4; mt++)
#pragma unroll
                for (int nt = 0; nt < 4; nt++)
                    mma_f16(acc[mt][nt], af[mt][0], af[mt][1], af[mt][2], af[mt][3],
                            bf[nt][0], bf[nt][1]);
        }

        const int n0 = it * 128;
#pragma unroll
        for (int mt = 0; mt < 4; mt++) {
            int r1 = warp_m + mt * 16 + grp;
            int r2 = r1 + 8;
#pragma unroll
            for (int nt = 0; nt < 4; nt++) {
                int col = n0 + warp_n + nt * 8 + 2 * qid;
                float e0 = fexp(fminf(acc[mt][nt][0] * 0.125f, 10.f));
                float e1 = fexp(fminf(acc[mt][nt][1] * 0.125f, 10.f));
                float e2 = fexp(fminf(acc[mt][nt][2] * 0.125f, 10.f));
                float e3 = fexp(fminf(acc[mt][nt][3] * 0.125f, 10.f));
                __half2 hA = __floats2half2_rn(e0, e1);
                __half2 hB = __floats2half2_rn(e2, e3);
                zlo[mt] += __low2float(hA) + __high2float(hA);
                zhi[mt] += __low2float(hB) + __high2float(hB);
                *(__half2*)(Sm + (size_t)(q0 + r1) * SS + col) = hA;
                *(__half2*)(Sm + (size_t)(q0 + r2) * SS + col) = hB;
            }
        }
        __syncthreads();
    }

#pragma unroll
    for (int o = 1; o <= 2; o <<= 1)
#pragma unroll
        for (int mt = 0; mt < 4; mt++) {
            zlo[mt] += __shfl_xor_sync(0xffffffffu, zlo[mt], o);
            zhi[mt] += __shfl_xor_sync(0xffffffffu, zhi[mt], o);
        }
    if (qid == 0) {
#pragma unroll
        for (int mt = 0; mt < 4; mt++) {
            sz[widn][warp_m + mt * 16 + grp]     = zlo[mt];
            sz[widn][warp_m + mt * 16 + grp + 8] = zhi[mt];
        }
    }
    __syncthreads();
    if (tid < 128) {
        float z = (sz[0][tid] + sz[1][tid]) + (sz[2][tid] + sz[3][tid]);
        g_Z[(size_t)bh * SS + q0 + tid] = z;
    }
}

// ============================================================================
// K3: PV — t = exp(e/Z1) packed to half2 A-frags; out = (t @ V)/Z2.
// E fp16 from g_S; V fp16 from g_Vt (already [w][s]). 8 warps all-m.
// ============================================================================
__global__ void __launch_bounds__(256, 2)
attn_pv_h(float* __restrict__ out) {
    extern __shared__ __half hsm3[];
    __half* Et = hsm3;                  // [2][128][HST]
    __half* Vt = hsm3 + 2 * 128 * HST;  // [2][64][HST]
    const uint32_t eBase = smem_u32(Et);
    const uint32_t vBase = smem_u32(Vt);

    const int bh = blockIdx.y;
    const int b  = bh >> 4, h = bh & 15;
    const int q0 = blockIdx.x * 128;
    const int tid  = threadIdx.x;
    const int wid  = tid >> 5;
    const int lane = tid & 31;
    const int grp  = lane >> 2;
    const int qid  = lane & 3;
    const __half* Sm = g_S + (size_t)bh * SS * SS;
    const __half* Vg = g_Vt + (size_t)bh * 64 * SS;

    const int rA = wid * 16 + grp;
    const int rB = rA + 8;
    const float invZa = 1.0f / g_Z[(size_t)bh * SS + q0 + rA];
    const float invZb = 1.0f / g_Z[(size_t)bh * SS + q0 + rB];

    // prologue: tile 0 (E: 128x64 halves; V: 64x64 halves)
#pragma unroll
    for (int t = 0; t < 4; t++) {
        int idx = tid + t * 256;
        int er = idx >> 3, ec = idx & 7;
        cp_async16(eBase + (uint32_t)(er * HST + ec * 8) * 2,
                   Sm + (size_t)(q0 + er) * SS + ec * 8);
    }
#pragma unroll
    for (int t = 0; t < 2; t++) {
        int idx = tid + t * 256;
        int vr = idx >> 3, vc = idx & 7;
        cp_async16(vBase + (uint32_t)(vr * HST + vc * 8) * 2,
                   Vg + (size_t)vr * SS + vc * 8);
    }
    cp_commit();

    float accPV[8][4];
#pragma unroll
    for (int nt = 0; nt < 8; nt++)
#pragma unroll
        for (int r = 0; r < 4; r++) accPV[nt][r] = 0.f;
    float z2a = 0.f, z2b = 0.f;

    for (int it = 0; it < 32; it++) {
        const int buf = it & 1;
        if (it + 1 < 32) {
            const int k1 = (it + 1) * 64;
#pragma unroll
            for (int t = 0; t < 4; t++) {
                int idx = tid + t * 256;
                int er = idx >> 3, ec = idx & 7;
                cp_async16(eBase + (uint32_t)((buf^1) * 128 * HST + er * HST + ec * 8) * 2,
                           Sm + (size_t)(q0 + er) * SS + k1 + ec * 8);
            }
#pragma unroll
            for (int t = 0; t < 2; t++) {
                int idx = tid + t * 256;
                int vr = idx >> 3, vc = idx & 7;
                cp_async16(vBase + (uint32_t)((buf^1) * 64 * HST + vr * HST + vc * 8) * 2,
                           Vg + (size_t)vr * SS + k1 + vc * 8);
            }
        }
        cp_commit();
        cp_wait1();
        __syncthreads();

        const __half* Eb = Et + buf * 128 * HST;
        const __half* Vb = Vt + buf * 64 * HST;

#pragma unroll
        for (int ks = 0; ks < 4; ks++) {
            const uint32_t* eA = (const uint32_t*)(Eb + rA * HST) + ks*8 + qid;
            const uint32_t* eB = (const uint32_t*)(Eb + rB * HST) + ks*8 + qid;
            float2 fa0 = __half22float2(*(const __half2*)&eA[0]);
            float2 fb0 = __half22float2(*(const __half2*)&eB[0]);
            float2 fa1 = __half22float2(*(const __half2*)&eA[4]);
            float2 fb1 = __half22float2(*(const __half2*)&eB[4]);
            float ta0 = fexp(fa0.x * invZa), ta1 = fexp(fa0.y * invZa);
            float tb0 = fexp(fb0.x * invZb), tb1 = fexp(fb0.y * invZb);
            float ta2 = fexp(fa1.x * invZa), ta3 = fexp(fa1.y * invZa);
            float tb2 = fexp(fb1.x * invZb), tb3 = fexp(fb1.y * invZb);
            z2a += (ta0 + ta1) + (ta2 + ta3);
            z2b += (tb0 + tb1) + (tb2 + tb3);
            __half2 hA0 = __floats2half2_rn(ta0, ta1);
            __half2 hB0 = __floats2half2_rn(tb0, tb1);
            __half2 hA1 = __floats2half2_rn(ta2, ta3);
            __half2 hB1 = __floats2half2_rn(tb2, tb3);
            uint32_t a0 = *(uint32_t*)&hA0, a1 = *(uint32_t*)&hB0;
            uint32_t a2 = *(uint32_t*)&hA1, a3 = *(uint32_t*)&hB1;
#pragma unroll
            for (int nt = 0; nt < 8; nt++) {
                const uint32_t* bp = (const uint32_t*)(Vb + (nt*8 + grp) * HST) + ks*8 + qid;
                mma_f16(accPV[nt], a0, a1, a2, a3, bp[0], bp[4]);
            }
        }
        __syncthreads();
    }

#pragma unroll
    for (int o = 1; o <= 2; o <<= 1) {
        z2a += __shfl_xor_sync(0xffffffffu, z2a, o);
        z2b += __shfl_xor_sync(0xffffffffu, z2b, o);
    }
    const float ra = 1.0f / z2a;
    const float rb = 1.0f / z2b;

#pragma unroll
    for (int nt = 0; nt < 8; nt++) {
        int col = h * HW + nt * 8 + 2 * qid;
        *(float2*)(out + (size_t)(b*SS + q0 + rA) * DD + col) =
            make_float2(accPV[nt][0] * ra, accPV[nt][1] * ra);
        *(float2*)(out + (size_t)(b*SS + q0 + rB) * DD + col) =
            make_float2(accPV[nt][2] * rb, accPV[nt][3] * rb);
    }
}

// ---------------- launch -----------------------------------------------------
extern "C" void kernel_launch(void* const* d_in, const int* in_sizes, int n_in,
                              void* d_out, int out_size) {
    const float* x  = (const float*)d_in[0];
    const float* Wq = (const float*)d_in[1];
    const float* bq = (const float*)d_in[2];
    const float* Wk = (const float*)d_in[3];
    const float* bk = (const float*)d_in[4];
    const float* Wv = (const float*)d_in[5];
    const float* bv = (const float*)d_in[6];
    float* out = (float*)d_out;

    const int smem_gemm = 4 * 128 * HST * sizeof(__half);               // 73728
    const int smem_sc   = 3 * 128 * HST * sizeof(__half);               // 55296
    const int smem_pv   = (2 * 128 + 2 * 64) * HST * sizeof(__half);    // 55296
    cudaFuncSetAttribute(gemm_h,
                         cudaFuncAttributeMaxDynamicSharedMemorySize, smem_gemm);
    cudaFuncSetAttribute(attn_scores_h,
                         cudaFuncAttributeMaxDynamicSharedMemorySize, smem_sc);
    cudaFuncSetAttribute(attn_pv_h,
                         cudaFuncAttributeMaxDynamicSharedMemorySize, smem_pv);

    to_half_k<<<dim3(512, 7), 256>>>(x, Wq, Wk, Wv);

    dim3 gproj(DD / 128, MM / 128, 3);          // (8, 32, 3)
    gemm_h<<<gproj, 256, smem_gemm>>>(bq, bk, bv);

    dim3 gs(SS / 128, BB * HH);                 // (16, 32)
    attn_scores_h<<<gs, 256, smem_sc>>>();
    attn_pv_h<<<gs, 256, smem_pv>>>(out);
}

// round 11
// speedup vs baseline: 2.4849x; 1.2115x over previous
#include <cuda_runtime.h>
#include <cuda_fp16.h>
#include <cstdint>
#include <math.h>

#define BB 2
#define SS 2048
#define DD 1024
#define HH 16
#define HW 64
#define MM (BB*SS)   // 4096

// ---------------- scratch (no cudaMalloc allowed) ---------------------------
__device__ __half g_xh[(size_t)MM * DD];                // 8 MB
__device__ __half g_Wh[3][(size_t)DD * DD];             // 6 MB
__device__ __half g_Qh[(size_t)MM * DD];                // 8 MB
__device__ __half g_Kh[(size_t)MM * DD];                // 8 MB
__device__ __half g_Vt[(size_t)MM * DD];                // 8 MB  V transposed per head: [bh][w][s]
__device__ __half g_S [(size_t)BB * HH * SS * SS];      // 256 MB (e^s fp16)
__device__ float  g_Z [(size_t)BB * HH * SS];           // Z1

// ---------------- PTX helpers (non-arch-specific only) ----------------------
__device__ __forceinline__ void mma_f16(float c[4],
                                        uint32_t a0, uint32_t a1, uint32_t a2, uint32_t a3,
                                        uint32_t b0, uint32_t b1) {
    asm volatile(
        "mma.sync.aligned.m16n8k16.row.col.f32.f16.f16.f32 "
        "{%0,%1,%2,%3}, {%4,%5,%6,%7}, {%8,%9}, {%0,%1,%2,%3};"
        : "+f"(c[0]), "+f"(c[1]), "+f"(c[2]), "+f"(c[3])
        : "r"(a0), "r"(a1), "r"(a2), "r"(a3), "r"(b0), "r"(b1));
}
__device__ __forceinline__ void ldsm_x4(uint32_t& r0, uint32_t& r1,
                                        uint32_t& r2, uint32_t& r3, uint32_t addr) {
    asm volatile("ldmatrix.sync.aligned.m8n8.x4.shared.b16 {%0,%1,%2,%3}, [%4];"
                 : "=r"(r0), "=r"(r1), "=r"(r2), "=r"(r3) : "r"(addr));
}
__device__ __forceinline__ uint32_t smem_u32(const void* p) {
    uint32_t a;
    asm("{ .reg .u64 t; cvta.to.shared.u64 t, %1; cvt.u32.u64 %0, t; }"
        : "=r"(a) : "l"(p));
    return a;
}
__device__ __forceinline__ void cp_async16(uint32_t s, const void* g) {
    asm volatile("cp.async.cg.shared.global [%0], [%1], 16;" :: "r"(s), "l"(g));
}
__device__ __forceinline__ void cp_commit() {
    asm volatile("cp.async.commit_group;" ::: "memory");
}
__device__ __forceinline__ void cp_wait1() {
    asm volatile("cp.async.wait_group 1;" ::: "memory");
}

// ---------------- exp variants ----------------------------------------------
// full-range exp (FFMA pipe, no MUFU)
__device__ __forceinline__ float fexp(float x) {
    float y = fmaxf(x * 1.4426950408889634f, -126.0f);
    float n = rintf(y);
    float f = y - n;
    float p =              1.5403530393381606e-4f;
    p = fmaf(p, f, 1.3333558146428443e-3f);
    p = fmaf(p, f, 9.6181291076284772e-3f);
    p = fmaf(p, f, 5.5504108664821580e-2f);
    p = fmaf(p, f, 2.4022650695910071e-1f);
    p = fmaf(p, f, 6.9314718055994531e-1f);
    p = fmaf(p, f, 1.0f);
    int e = (((int)n) + 127) << 23;
    return p * __int_as_float(e);
}
// exp for p in [0, ~1]: degree-7 Taylor, rel err <= 1.1e-5, 7 FMAs
__device__ __forceinline__ float texp01(float p) {
    float r = 1.984126984e-4f;                 // 1/5040
    r = fmaf(r, p, 1.388888889e-3f);           // 1/720
    r = fmaf(r, p, 8.333333333e-3f);           // 1/120
    r = fmaf(r, p, 4.166666667e-2f);           // 1/24
    r = fmaf(r, p, 1.666666667e-1f);           // 1/6
    r = fmaf(r, p, 0.5f);
    r = fmaf(r, p, 1.0f);
    r = fmaf(r, p, 1.0f);
    return r;
}

// ============================================================================
// K0: fp32 -> fp16 convert
// ============================================================================
__global__ void __launch_bounds__(256)
to_half_k(const float* __restrict__ x,  const float* __restrict__ Wq,
          const float* __restrict__ Wk, const float* __restrict__ Wv) {
    const int seg = blockIdx.y;
    const size_t idx = ((size_t)blockIdx.x * 256 + threadIdx.x) * 8;
    const float* src;
    __half* dst;
    if (seg < 4) { src = x + (size_t)seg * 1048576; dst = g_xh + (size_t)seg * 1048576; }
    else if (seg == 4) { src = Wq; dst = g_Wh[0]; }
    else if (seg == 5) { src = Wk; dst = g_Wh[1]; }
    else               { src = Wv; dst = g_Wh[2]; }
    float4 a = *(const float4*)(src + idx);
    float4 b = *(const float4*)(src + idx + 4);
    __half2 h0 = __floats2half2_rn(a.x, a.y);
    __half2 h1 = __floats2half2_rn(a.z, a.w);
    __half2 h2 = __floats2half2_rn(b.x, b.y);
    __half2 h3 = __floats2half2_rn(b.z, b.w);
    uint4 o;
    o.x = *(uint32_t*)&h0; o.y = *(uint32_t*)&h1;
    o.z = *(uint32_t*)&h2; o.w = *(uint32_t*)&h3;
    *(uint4*)(dst + idx) = o;
}

#define HST  72             // tile row stride in halves
#define HSTB (HST * 2)      // ... in bytes

// per-lane ldmatrix byte offsets within a tile (row stride HSTB)
// A-type (16 rows x 16 halves): m = lane>>3; row += (m&1)*8 + (lane&7); colbytes = (m>>1)*16
#define LDSM_OFF_A(lane) ((uint32_t)((((lane) & 7) + (((lane) >> 3) & 1) * 8) * HSTB + ((lane) >> 4) * 16))
// B-type (16 n-rows x 16 halves): row += (lane>>4)*8 + (lane&7); colbytes = ((lane>>3)&1)*16
#define LDSM_OFF_B(lane) ((uint32_t)((((lane) & 7) + ((lane) >> 4) * 8) * HSTB + (((lane) >> 3) & 1) * 16))

// ============================================================================
// K1: fp16 m16n8k16 GEMM  C = X @ W^T + b. CTA 128x128, BK=64, 8 warps (2m x 4n)
// ============================================================================
__global__ void __launch_bounds__(256, 2)
gemm_h(const float* __restrict__ bq, const float* __restrict__ bk,
       const float* __restrict__ bv) {
    const int which = blockIdx.z;
    const __half* W    = g_Wh[which];
    const float* bias  = (which == 0) ? bq : (which == 1) ? bk : bv;

    extern __shared__ __half hsm[];
    __half* At = hsm;                  // [2][128][HST]
    __half* Bt = hsm + 2 * 128 * HST;  // [2][128][HST]
    const uint32_t aBase = smem_u32(At);
    const uint32_t bBase = smem_u32(Bt);

    const int tid  = threadIdx.x;
    const int wid  = tid >> 5;
    const int lane = tid & 31;
    const int qid  = lane & 3;
    const int m0 = blockIdx.y * 128;
    const int n0 = blockIdx.x * 128;
    const int warp_m = (wid & 1) * 64;
    const int warp_n = (wid >> 1) * 32;
    const int grp  = lane >> 2;

    const uint32_t offA = LDSM_OFF_A(lane);
    const uint32_t offB = LDSM_OFF_B(lane);

    // prologue: tile 0
#pragma unroll
    for (int t = 0; t < 4; t++) {
        int idx = tid + t * 256;
        int row = idx >> 3;
        int c8  = idx & 7;
        cp_async16(aBase + (uint32_t)(row * HST + c8 * 8) * 2,
                   g_xh + (size_t)(m0 + row) * DD + c8 * 8);
        cp_async16(bBase + (uint32_t)(row * HST + c8 * 8) * 2,
                   W + (size_t)(n0 + row) * DD + c8 * 8);
    }
    cp_commit();

    float acc[4][4][4];
#pragma unroll
    for (int mt = 0; mt < 4; mt++)
#pragma unroll
        for (int nt = 0; nt < 4; nt++)
#pragma unroll
            for (int r = 0; r < 4; r++) acc[mt][nt][r] = 0.f;

    for (int kc = 0; kc < 16; kc++) {
        const int buf = kc & 1;
        if (kc + 1 < 16) {
            const int k1 = (kc + 1) * 64;
#pragma unroll
            for (int t = 0; t < 4; t++) {
                int idx = tid + t * 256;
                int row = idx >> 3;
                int c8  = idx & 7;
                cp_async16(aBase + (uint32_t)((buf^1) * 128 * HST + row * HST + c8 * 8) * 2,
                           g_xh + (size_t)(m0 + row) * DD + k1 + c8 * 8);
                cp_async16(bBase + (uint32_t)((buf^1) * 128 * HST + row * HST + c8 * 8) * 2,
                           W + (size_t)(n0 + row) * DD + k1 + c8 * 8);
            }
        }
        cp_commit();
        cp_wait1();
        __syncthreads();

        const uint32_t aT = aBase + buf * 128 * HSTB + warp_m * HSTB + offA;
        const uint32_t bT = bBase + buf * 128 * HSTB + warp_n * HSTB + offB;
#pragma unroll
        for (int ks = 0; ks < 4; ks++) {
            uint32_t af[4][4], bf[4][2];
#pragma unroll
            for (int mt = 0; mt < 4; mt++)
                ldsm_x4(af[mt][0], af[mt][1], af[mt][2], af[mt][3],
                        aT + mt * 16 * HSTB + ks * 32);
#pragma unroll
            for (int ntp = 0; ntp < 2; ntp++)
                ldsm_x4(bf[2*ntp][0], bf[2*ntp][1], bf[2*ntp+1][0], bf[2*ntp+1][1],
                        bT + ntp * 16 * HSTB + ks * 32);
#pragma unroll
            for (int mt = 0; mt < 4; mt++)
#pragma unroll
                for (int nt = 0; nt < 4; nt++)
                    mma_f16(acc[mt][nt], af[mt][0], af[mt][1], af[mt][2], af[mt][3],
                            bf[nt][0], bf[nt][1]);
        }
        __syncthreads();
    }

    if (which < 2) {
        __half* C = (which == 0) ? g_Qh : g_Kh;
#pragma unroll
        for (int mt = 0; mt < 4; mt++) {
#pragma unroll
            for (int nt = 0; nt < 4; nt++) {
                int col = n0 + warp_n + nt * 8 + 2 * qid;
                float bx = bias[col], by = bias[col + 1];
                int r0 = m0 + warp_m + mt * 16 + grp;
                __half2 o0 = __floats2half2_rn(acc[mt][nt][0] + bx, acc[mt][nt][1] + by);
                __half2 o1 = __floats2half2_rn(acc[mt][nt][2] + bx, acc[mt][nt][3] + by);
                *(__half2*)(C + (size_t)r0 * DD + col) = o0;
                *(__half2*)(C + (size_t)(r0 + 8) * DD + col) = o1;
            }
        }
    } else {
#pragma unroll
        for (int mt = 0; mt < 4; mt++) {
#pragma unroll
            for (int nt = 0; nt < 4; nt++) {
                int col = n0 + warp_n + nt * 8 + 2 * qid;
                float bx = bias[col], by = bias[col + 1];
                int r0 = m0 + warp_m + mt * 16 + grp;
                int hh = col >> 6, w = col & 63;
                int b1 = r0 >> 11, s1 = r0 & 2047;
                size_t base = ((size_t)(b1 * 16 + hh) * 64);
                g_Vt[(base + w    ) * SS + s1]     = __float2half(acc[mt][nt][0] + bx);
                g_Vt[(base + w + 1) * SS + s1]     = __float2half(acc[mt][nt][1] + by);
                g_Vt[(base + w    ) * SS + s1 + 8] = __float2half(acc[mt][nt][2] + bx);
                g_Vt[(base + w + 1) * SS + s1 + 8] = __float2half(acc[mt][nt][3] + by);
            }
        }
    }
}

// ============================================================================
// K2: scores — e = exp(s/8) (fp16) -> g_S, Z1 -> g_Z. ldmatrix fragments.
// ============================================================================
__global__ void __launch_bounds__(256, 2)
attn_scores_h() {
    extern __shared__ __half hsm2[];
    __half* Qs = hsm2;                  // [128][HST]
    __half* Kt = hsm2 + 128 * HST;      // [2][128][HST]
    __shared__ float sz[4][128];
    const uint32_t qBase = smem_u32(Qs);
    const uint32_t kBase = smem_u32(Kt);

    const int bh = blockIdx.y;
    const int b  = bh >> 4, h = bh & 15;
    const int q0 = blockIdx.x * 128;
    const int tid  = threadIdx.x;
    const int wid  = tid >> 5;
    const int lane = tid & 31;
    const int grp  = lane >> 2;
    const int qid  = lane & 3;
    const int widm = wid & 1, widn = wid >> 1;
    const int warp_m = widm * 64, warp_n = widn * 32;
    __half* Sm = g_S + (size_t)bh * SS * SS;

    const uint32_t offA = LDSM_OFF_A(lane);
    const uint32_t offB = LDSM_OFF_B(lane);

#pragma unroll
    for (int t = 0; t < 4; t++) {
        int idx = tid + t * 256;
        int row = idx >> 3;
        int c8  = idx & 7;
        cp_async16(kBase + (uint32_t)(row * HST + c8 * 8) * 2,
                   g_Kh + (size_t)(b*SS + row) * DD + h*HW + c8*8);
    }
    cp_commit();

#pragma unroll
    for (int t = 0; t < 4; t++) {
        int idx = tid + t * 256;
        int row = idx >> 3;
        int c8  = idx & 7;
        uint4 v = *(const uint4*)(g_Qh + (size_t)(b*SS + q0 + row) * DD + h*HW + c8*8);
        *(uint4*)(Qs + row * HST + c8 * 8) = v;
    }

    float zlo[4] = {0.f,0.f,0.f,0.f}, zhi[4] = {0.f,0.f,0.f,0.f};

    for (int it = 0; it < 16; it++) {
        const int buf = it & 1;
        if (it + 1 < 16) {
            const int n1 = (it + 1) * 128;
#pragma unroll
            for (int t = 0; t < 4; t++) {
                int idx = tid + t * 256;
                int row = idx >> 3;
                int c8  = idx & 7;
                cp_async16(kBase + (uint32_t)((buf^1) * 128 * HST + row * HST + c8 * 8) * 2,
                           g_Kh + (size_t)(b*SS + n1 + row) * DD + h*HW + c8*8);
            }
        }
        cp_commit();
        cp_wait1();
        __syncthreads();

        float acc[4][4][4];
#pragma unroll
        for (int mt = 0; mt < 4; mt++)
#pragma unroll
            for (int nt = 0; nt < 4; nt++)
#pragma unroll
                for (int r = 0; r < 4; r++) acc[mt][nt][r] = 0.f;

        const uint32_t qT = qBase + warp_m * HSTB + offA;
        const uint32_t kT = kBase + buf * 128 * HSTB + warp_n * HSTB + offB;
#pragma unroll
        for (int ks = 0; ks < 4; ks++) {
            uint32_t af[4][4], bf[4][2];
#pragma unroll
            for (int mt = 0; mt < 4; mt++)
                ldsm_x4(af[mt][0], af[mt][1], af[mt][2], af[mt][3],
                        qT + mt * 16 * HSTB + ks * 32);
#pragma unroll
            for (int ntp = 0; ntp < 2; ntp++)
                ldsm_x4(bf[2*ntp][0], bf[2*ntp][1], bf[2*ntp+1][0], bf[2*ntp+1][1],
                        kT + ntp * 16 * HSTB + ks * 32);
#pragma unroll
            for (int mt = 0; mt < 4; mt++)
#pragma unroll
                for (int nt = 0; nt < 4; nt++)
                    mma_f16(acc[mt][nt], af[mt][0], af[mt][1], af[mt][2], af[mt][3],
                            bf[nt][0], bf[nt][1]);
        }

        const int n0 = it * 128;
#pragma unroll
        for (int mt = 0; mt < 4; mt++) {
            int r1 = warp_m + mt * 16 + grp;
            int r2 = r1 + 8;
#pragma unroll
            for (int nt = 0; nt < 4; nt++) {
                int col = n0 + warp_n + nt * 8 + 2 * qid;
                float e0 = fexp(fminf(acc[mt][nt][0] * 0.125f, 10.f));
                float e1 = fexp(fminf(acc[mt][nt][1] * 0.125f, 10.f));
                float e2 = fexp(fminf(acc[mt][nt][2] * 0.125f, 10.f));
                float e3 = fexp(fminf(acc[mt][nt][3] * 0.125f, 10.f));
                __half2 hA = __floats2half2_rn(e0, e1);
                __half2 hB = __floats2half2_rn(e2, e3);
                zlo[mt] += __low2float(hA) + __high2float(hA);
                zhi[mt] += __low2float(hB) + __high2float(hB);
                *(__half2*)(Sm + (size_t)(q0 + r1) * SS + col) = hA;
                *(__half2*)(Sm + (size_t)(q0 + r2) * SS + col) = hB;
            }
        }
        __syncthreads();
    }

#pragma unroll
    for (int o = 1; o <= 2; o <<= 1)
#pragma unroll
        for (int mt = 0; mt < 4; mt++) {
            zlo[mt] += __shfl_xor_sync(0xffffffffu, zlo[mt], o);
            zhi[mt] += __shfl_xor_sync(0xffffffffu, zhi[mt], o);
        }
    if (qid == 0) {
#pragma unroll
        for (int mt = 0; mt < 4; mt++) {
            sz[widn][warp_m + mt * 16 + grp]     = zlo[mt];
            sz[widn][warp_m + mt * 16 + grp + 8] = zhi[mt];
        }
    }
    __syncthreads();
    if (tid < 128) {
        float z = (sz[0][tid] + sz[1][tid]) + (sz[2][tid] + sz[3][tid]);
        g_Z[(size_t)bh * SS + q0 + tid] = z;
    }
}

// ============================================================================
// K3: PV — t = texp01(e/Z1); out = (t @ V)/Z2. ldmatrix for E and V fragments.
// ============================================================================
__global__ void __launch_bounds__(256, 2)
attn_pv_h(float* __restrict__ out) {
    extern __shared__ __half hsm3[];
    __half* Et = hsm3;                  // [2][128][HST]
    __half* Vt = hsm3 + 2 * 128 * HST;  // [2][64][HST]
    const uint32_t eBase = smem_u32(Et);
    const uint32_t vBase = smem_u32(Vt);

    const int bh = blockIdx.y;
    const int b  = bh >> 4, h = bh & 15;
    const int q0 = blockIdx.x * 128;
    const int tid  = threadIdx.x;
    const int wid  = tid >> 5;
    const int lane = tid & 31;
    const int grp  = lane >> 2;
    const int qid  = lane & 3;
    const __half* Sm = g_S + (size_t)bh * SS * SS;
    const __half* Vg = g_Vt + (size_t)bh * 64 * SS;

    const int rA = wid * 16 + grp;
    const int rB = rA + 8;
    const float invZa = 1.0f / g_Z[(size_t)bh * SS + q0 + rA];
    const float invZb = 1.0f / g_Z[(size_t)bh * SS + q0 + rB];

    const uint32_t offA = LDSM_OFF_A(lane);
    const uint32_t offB = LDSM_OFF_B(lane);

#pragma unroll
    for (int t = 0; t < 4; t++) {
        int idx = tid + t * 256;
        int er = idx >> 3, ec = idx & 7;
        cp_async16(eBase + (uint32_t)(er * HST + ec * 8) * 2,
                   Sm + (size_t)(q0 + er) * SS + ec * 8);
    }
#pragma unroll
    for (int t = 0; t < 2; t++) {
        int idx = tid + t * 256;
        int vr = idx >> 3, vc = idx & 7;
        cp_async16(vBase + (uint32_t)(vr * HST + vc * 8) * 2,
                   Vg + (size_t)vr * SS + vc * 8);
    }
    cp_commit();

    float accPV[8][4];
#pragma unroll
    for (int nt = 0; nt < 8; nt++)
#pragma unroll
        for (int r = 0; r < 4; r++) accPV[nt][r] = 0.f;
    float z2a = 0.f, z2b = 0.f;

    for (int it = 0; it < 32; it++) {
        const int buf = it & 1;
        if (it + 1 < 32) {
            const int k1 = (it + 1) * 64;
#pragma unroll
            for (int t = 0; t < 4; t++) {
                int idx = tid + t * 256;
                int er = idx >> 3, ec = idx & 7;
                cp_async16(eBase + (uint32_t)((buf^1) * 128 * HST + er * HST + ec * 8) * 2,
                           Sm + (size_t)(q0 + er) * SS + k1 + ec * 8);
            }
#pragma unroll
            for (int t = 0; t < 2; t++) {
                int idx = tid + t * 256;
                int vr = idx >> 3, vc = idx & 7;
                cp_async16(vBase + (uint32_t)((buf^1) * 64 * HST + vr * HST + vc * 8) * 2,
                           Vg + (size_t)vr * SS + k1 + vc * 8);
            }
        }
        cp_commit();
        cp_wait1();
        __syncthreads();

        const uint32_t eT = eBase + buf * 128 * HSTB + wid * 16 * HSTB + offA;
        const uint32_t vT = vBase + buf * 64 * HSTB + offB;

#pragma unroll
        for (int ks = 0; ks < 4; ks++) {
            // E fragment via one ldmatrix: r0=(rA,k), r1=(rB,k), r2=(rA,k+8), r3=(rB,k+8)
            uint32_t e0, e1, e2, e3;
            ldsm_x4(e0, e1, e2, e3, eT + ks * 32);
            float2 fa0 = __half22float2(*(__half2*)&e0);
            float2 fb0 = __half22float2(*(__half2*)&e1);
            float2 fa1 = __half22float2(*(__half2*)&e2);
            float2 fb1 = __half22float2(*(__half2*)&e3);
            float ta0 = texp01(fa0.x * invZa), ta1 = texp01(fa0.y * invZa);
            float tb0 = texp01(fb0.x * invZb), tb1 = texp01(fb0.y * invZb);
            float ta2 = texp01(fa1.x * invZa), ta3 = texp01(fa1.y * invZa);
            float tb2 = texp01(fb1.x * invZb), tb3 = texp01(fb1.y * invZb);
            z2a += (ta0 + ta1) + (ta2 + ta3);
            z2b += (tb0 + tb1) + (tb2 + tb3);
            __half2 hA0 = __floats2half2_rn(ta0, ta1);
            __half2 hB0 = __floats2half2_rn(tb0, tb1);
            __half2 hA1 = __floats2half2_rn(ta2, ta3);
            __half2 hB1 = __floats2half2_rn(tb2, tb3);
            uint32_t a0 = *(uint32_t*)&hA0, a1 = *(uint32_t*)&hB0;
            uint32_t a2 = *(uint32_t*)&hA1, a3 = *(uint32_t*)&hB1;

            uint32_t bf[8][2];
#pragma unroll
            for (int ntp = 0; ntp < 4; ntp++)
                ldsm_x4(bf[2*ntp][0], bf[2*ntp][1], bf[2*ntp+1][0], bf[2*ntp+1][1],
                        vT + ntp * 16 * HSTB + ks * 32);
#pragma unroll
            for (int nt = 0; nt < 8; nt++)
                mma_f16(accPV[nt], a0, a1, a2, a3, bf[nt][0], bf[nt][1]);
        }
        __syncthreads();
    }

#pragma unroll
    for (int o = 1; o <= 2; o <<= 1) {
        z2a += __shfl_xor_sync(0xffffffffu, z2a, o);
        z2b += __shfl_xor_sync(0xffffffffu, z2b, o);
    }
    const float ra = 1.0f / z2a;
    const float rb = 1.0f / z2b;

#pragma unroll
    for (int nt = 0; nt < 8; nt++) {
        int col = h * HW + nt * 8 + 2 * qid;
        *(float2*)(out + (size_t)(b*SS + q0 + rA) * DD + col) =
            make_float2(accPV[nt][0] * ra, accPV[nt][1] * ra);
        *(float2*)(out + (size_t)(b*SS + q0 + rB) * DD + col) =
            make_float2(accPV[nt][2] * rb, accPV[nt][3] * rb);
    }
}

// ---------------- launch -----------------------------------------------------
extern "C" void kernel_launch(void* const* d_in, const int* in_sizes, int n_in,
                              void* d_out, int out_size) {
    const float* x  = (const float*)d_in[0];
    const float* Wq = (const float*)d_in[1];
    const float* bq = (const float*)d_in[2];
    const float* Wk = (const float*)d_in[3];
    const float* bk = (const float*)d_in[4];
    const float* Wv = (const float*)d_in[5];
    const float* bv = (const float*)d_in[6];
    float* out = (float*)d_out;

    const int smem_gemm = 4 * 128 * HST * sizeof(__half);               // 73728
    const int smem_sc   = 3 * 128 * HST * sizeof(__half);               // 55296
    const int smem_pv   = (2 * 128 + 2 * 64) * HST * sizeof(__half);    // 55296
    cudaFuncSetAttribute(gemm_h,
                         cudaFuncAttributeMaxDynamicSharedMemorySize, smem_gemm);
    cudaFuncSetAttribute(attn_scores_h,
                         cudaFuncAttributeMaxDynamicSharedMemorySize, smem_sc);
    cudaFuncSetAttribute(attn_pv_h,
                         cudaFuncAttributeMaxDynamicSharedMemorySize, smem_pv);

    to_half_k<<<dim3(512, 7), 256>>>(x, Wq, Wk, Wv);

    dim3 gproj(DD / 128, MM / 128, 3);          // (8, 32, 3)
    gemm_h<<<gproj, 256, smem_gemm>>>(bq, bk, bv);

    dim3 gs(SS / 128, BB * HH);                 // (16, 32)
    attn_scores_h<<<gs, 256, smem_sc>>>();
    attn_pv_h<<<gs, 256, smem_pv>>>(out);
}

// round 13
// speedup vs baseline: 2.7038x; 1.0881x over previous
#include <cuda_runtime.h>
#include <cuda_fp16.h>
#include <cstdint>
#include <math.h>

#define BB 2
#define SS 2048
#define DD 1024
#define HH 16
#define HW 64
#define MM (BB*SS)   // 4096

// ---------------- scratch (no cudaMalloc allowed) ---------------------------
__device__ __half g_xh[(size_t)MM * DD];                // 8 MB
__device__ __half g_Wh[3][(size_t)DD * DD];             // 6 MB
__device__ __half g_Qh[(size_t)MM * DD];                // 8 MB
__device__ __half g_Kh[(size_t)MM * DD];                // 8 MB
__device__ __half g_Vt[(size_t)MM * DD];                // 8 MB  V transposed per head: [bh][w][s]
__device__ __half g_S [(size_t)BB * HH * SS * SS];      // 256 MB (e^s fp16)
__device__ float  g_Z [(size_t)BB * HH * SS];           // Z1

// ---------------- PTX helpers (non-arch-specific only) ----------------------
__device__ __forceinline__ void mma_f16(float c[4],
                                        uint32_t a0, uint32_t a1, uint32_t a2, uint32_t a3,
                                        uint32_t b0, uint32_t b1) {
    asm volatile(
        "mma.sync.aligned.m16n8k16.row.col.f32.f16.f16.f32 "
        "{%0,%1,%2,%3}, {%4,%5,%6,%7}, {%8,%9}, {%0,%1,%2,%3};"
        : "+f"(c[0]), "+f"(c[1]), "+f"(c[2]), "+f"(c[3])
        : "r"(a0), "r"(a1), "r"(a2), "r"(a3), "r"(b0), "r"(b1));
}
__device__ __forceinline__ void ldsm_x4(uint32_t& r0, uint32_t& r1,
                                        uint32_t& r2, uint32_t& r3, uint32_t addr) {
    asm volatile("ldmatrix.sync.aligned.m8n8.x4.shared.b16 {%0,%1,%2,%3}, [%4];"
                 : "=r"(r0), "=r"(r1), "=r"(r2), "=r"(r3) : "r"(addr));
}
__device__ __forceinline__ uint32_t smem_u32(const void* p) {
    uint32_t a;
    asm("{ .reg .u64 t; cvta.to.shared.u64 t, %1; cvt.u32.u64 %0, t; }"
        : "=r"(a) : "l"(p));
    return a;
}
__device__ __forceinline__ void cp_async16(uint32_t s, const void* g) {
    asm volatile("cp.async.cg.shared.global [%0], [%1], 16;" :: "r"(s), "l"(g));
}
__device__ __forceinline__ void cp_commit() {
    asm volatile("cp.async.commit_group;" ::: "memory");
}
__device__ __forceinline__ void cp_wait1() {
    asm volatile("cp.async.wait_group 1;" ::: "memory");
}

// ---------------- half2 exp variants ----------------------------------------
// e^(acc * 0.125) for a pair of fp32 scores — fully half2 after the pack.
// y = s*log2e packed to fp16; n via magic-add rint; 2^f deg-4 HFMA2 poly;
// 2^n constructed with 3 packed integer ops.  Clamp y to [-14, 14].
__device__ __forceinline__ __half2 hexp2s(float s0, float s1) {
    const float C8 = 0.18033688f;            // 0.125 * log2(e)
    __half2 y2 = __floats2half2_rn(s0 * C8, s1 * C8);
    y2 = __hmin2(__hmax2(y2, __floats2half2_rn(-14.f, -14.f)),
                 __floats2half2_rn(14.f, 14.f));
    const __half2 magic = __floats2half2_rn(1536.f, 1536.f);
    __half2 z2 = __hadd2(y2, magic);         // rint into mantissa
    __half2 n2 = __hsub2(z2, magic);         // exact integer halves
    __half2 f2 = __hsub2(y2, n2);            // [-0.5, 0.5]
    __half2 p  = __floats2half2_rn(0.00961813f, 0.00961813f);
    p = __hfma2(p, f2, __floats2half2_rn(0.05550411f, 0.05550411f));
    p = __hfma2(p, f2, __floats2half2_rn(0.24022651f, 0.24022651f));
    p = __hfma2(p, f2, __floats2half2_rn(0.69314718f, 0.69314718f));
    p = __hfma2(p, f2, __floats2half2_rn(1.0f, 1.0f));
    uint32_t zb = *(uint32_t*)&z2;
    uint32_t sb = ((zb - 0x65F165F1u) & 0x001F001Fu) << 10;   // bits of 2^n
    return __hmul2(p, *(__half2*)&sb);
}
// exp(e * invZ) for p in [0,~1]: deg-4 Taylor, all half2 (input/out = fragments)
__device__ __forceinline__ __half2 texp_h2(__half2 e2, __half2 iz2) {
    __half2 p = __hmul2(e2, iz2);
    __half2 r = __floats2half2_rn(4.1666668e-2f, 4.1666668e-2f);   // 1/24
    r = __hfma2(r, p, __floats2half2_rn(1.6666667e-1f, 1.6666667e-1f));
    r = __hfma2(r, p, __floats2half2_rn(0.5f, 0.5f));
    r = __hfma2(r, p, __floats2half2_rn(1.0f, 1.0f));
    r = __hfma2(r, p, __floats2half2_rn(1.0f, 1.0f));
    return r;
}

// ============================================================================
// K0: fp32 -> fp16 convert
// ============================================================================
__global__ void __launch_bounds__(256)
to_half_k(const float* __restrict__ x,  const float* __restrict__ Wq,
          const float* __restrict__ Wk, const float* __restrict__ Wv) {
    const int seg = blockIdx.y;
    const size_t idx = ((size_t)blockIdx.x * 256 + threadIdx.x) * 8;
    const float* src;
    __half* dst;
    if (seg < 4) { src = x + (size_t)seg * 1048576; dst = g_xh + (size_t)seg * 1048576; }
    else if (seg == 4) { src = Wq; dst = g_Wh[0]; }
    else if (seg == 5) { src = Wk; dst = g_Wh[1]; }
    else               { src = Wv; dst = g_Wh[2]; }
    float4 a = *(const float4*)(src + idx);
    float4 b = *(const float4*)(src + idx + 4);
    __half2 h0 = __floats2half2_rn(a.x, a.y);
    __half2 h1 = __floats2half2_rn(a.z, a.w);
    __half2 h2 = __floats2half2_rn(b.x, b.y);
    __half2 h3 = __floats2half2_rn(b.z, b.w);
    uint4 o;
    o.x = *(uint32_t*)&h0; o.y = *(uint32_t*)&h1;
    o.z = *(uint32_t*)&h2; o.w = *(uint32_t*)&h3;
    *(uint4*)(dst + idx) = o;
}

#define HST  72             // tile row stride in halves
#define HSTB (HST * 2)      // ... in bytes

#define LDSM_OFF_A(lane) ((uint32_t)((((lane) & 7) + (((lane) >> 3) & 1) * 8) * HSTB + ((lane) >> 4) * 16))
#define LDSM_OFF_B(lane) ((uint32_t)((((lane) & 7) + ((lane) >> 4) * 8) * HSTB + (((lane) >> 3) & 1) * 16))

// ============================================================================
// K1: fp16 m16n8k16 GEMM  C = X @ W^T + b. CTA 128x128, BK=64, 8 warps (2m x 4n)
// ============================================================================
__global__ void __launch_bounds__(256, 2)
gemm_h(const float* __restrict__ bq, const float* __restrict__ bk,
       const float* __restrict__ bv) {
    const int which = blockIdx.z;
    const __half* W    = g_Wh[which];
    const float* bias  = (which == 0) ? bq : (which == 1) ? bk : bv;

    extern __shared__ __half hsm[];
    __half* At = hsm;                  // [2][128][HST]
    __half* Bt = hsm + 2 * 128 * HST;  // [2][128][HST]
    const uint32_t aBase = smem_u32(At);
    const uint32_t bBase = smem_u32(Bt);

    const int tid  = threadIdx.x;
    const int wid  = tid >> 5;
    const int lane = tid & 31;
    const int qid  = lane & 3;
    const int m0 = blockIdx.y * 128;
    const int n0 = blockIdx.x * 128;
    const int warp_m = (wid & 1) * 64;
    const int warp_n = (wid >> 1) * 32;
    const int grp  = lane >> 2;

    const uint32_t offA = LDSM_OFF_A(lane);
    const uint32_t offB = LDSM_OFF_B(lane);

#pragma unroll
    for (int t = 0; t < 4; t++) {
        int idx = tid + t * 256;
        int row = idx >> 3;
        int c8  = idx & 7;
        cp_async16(aBase + (uint32_t)(row * HST + c8 * 8) * 2,
                   g_xh + (size_t)(m0 + row) * DD + c8 * 8);
        cp_async16(bBase + (uint32_t)(row * HST + c8 * 8) * 2,
                   W + (size_t)(n0 + row) * DD + c8 * 8);
    }
    cp_commit();

    float acc[4][4][4];
#pragma unroll
    for (int mt = 0; mt < 4; mt++)
#pragma unroll
        for (int nt = 0; nt < 4; nt++)
#pragma unroll
            for (int r = 0; r < 4; r++) acc[mt][nt][r] = 0.f;

    for (int kc = 0; kc < 16; kc++) {
        const int buf = kc & 1;
        if (kc + 1 < 16) {
            const int k1 = (kc + 1) * 64;
#pragma unroll
            for (int t = 0; t < 4; t++) {
                int idx = tid + t * 256;
                int row = idx >> 3;
                int c8  = idx & 7;
                cp_async16(aBase + (uint32_t)((buf^1) * 128 * HST + row * HST + c8 * 8) * 2,
                           g_xh + (size_t)(m0 + row) * DD + k1 + c8 * 8);
                cp_async16(bBase + (uint32_t)((buf^1) * 128 * HST + row * HST + c8 * 8) * 2,
                           W + (size_t)(n0 + row) * DD + k1 + c8 * 8);
            }
        }
        cp_commit();
        cp_wait1();
        __syncthreads();

        const uint32_t aT = aBase + buf * 128 * HSTB + warp_m * HSTB + offA;
        const uint32_t bT = bBase + buf * 128 * HSTB + warp_n * HSTB + offB;
#pragma unroll
        for (int ks = 0; ks < 4; ks++) {
            uint32_t af[4][4], bf[4][2];
#pragma unroll
            for (int mt = 0; mt < 4; mt++)
                ldsm_x4(af[mt][0], af[mt][1], af[mt][2], af[mt][3],
                        aT + mt * 16 * HSTB + ks * 32);
#pragma unroll
            for (int ntp = 0; ntp < 2; ntp++)
                ldsm_x4(bf[2*ntp][0], bf[2*ntp][1], bf[2*ntp+1][0], bf[2*ntp+1][1],
                        bT + ntp * 16 * HSTB + ks * 32);
#pragma unroll
            for (int mt = 0; mt < 4; mt++)
#pragma unroll
                for (int nt = 0; nt < 4; nt++)
                    mma_f16(acc[mt][nt], af[mt][0], af[mt][1], af[mt][2], af[mt][3],
                            bf[nt][0], bf[nt][1]);
        }
        __syncthreads();
    }

    if (which < 2) {
        __half* C = (which == 0) ? g_Qh : g_Kh;
#pragma unroll
        for (int mt = 0; mt < 4; mt++) {
#pragma unroll
            for (int nt = 0; nt < 4; nt++) {
                int col = n0 + warp_n + nt * 8 + 2 * qid;
                float bx = bias[col], by = bias[col + 1];
                int r0 = m0 + warp_m + mt * 16 + grp;
                __half2 o0 = __floats2half2_rn(acc[mt][nt][0] + bx, acc[mt][nt][1] + by);
                __half2 o1 = __floats2half2_rn(acc[mt][nt][2] + bx, acc[mt][nt][3] + by);
                *(__half2*)(C + (size_t)r0 * DD + col) = o0;
                *(__half2*)(C + (size_t)(r0 + 8) * DD + col) = o1;
            }
        }
    } else {
#pragma unroll
        for (int mt = 0; mt < 4; mt++) {
#pragma unroll
            for (int nt = 0; nt < 4; nt++) {
                int col = n0 + warp_n + nt * 8 + 2 * qid;
                float bx = bias[col], by = bias[col + 1];
                int r0 = m0 + warp_m + mt * 16 + grp;
                int hh = col >> 6, w = col & 63;
                int b1 = r0 >> 11, s1 = r0 & 2047;
                size_t base = ((size_t)(b1 * 16 + hh) * 64);
                g_Vt[(base + w    ) * SS + s1]     = __float2half(acc[mt][nt][0] + bx);
                g_Vt[(base + w + 1) * SS + s1]     = __float2half(acc[mt][nt][1] + by);
                g_Vt[(base + w    ) * SS + s1 + 8] = __float2half(acc[mt][nt][2] + bx);
                g_Vt[(base + w + 1) * SS + s1 + 8] = __float2half(acc[mt][nt][3] + by);
            }
        }
    }
}

// ============================================================================
// K2: scores — e = exp(s/8) via half2 magic exp -> g_S, Z1 -> g_Z
// ============================================================================
__global__ void __launch_bounds__(256, 2)
attn_scores_h() {
    extern __shared__ __half hsm2[];
    __half* Qs = hsm2;                  // [128][HST]
    __half* Kt = hsm2 + 128 * HST;      // [2][128][HST]
    __shared__ float sz[4][128];
    const uint32_t qBase = smem_u32(Qs);
    const uint32_t kBase = smem_u32(Kt);

    const int bh = blockIdx.y;
    const int b  = bh >> 4, h = bh & 15;
    const int q0 = blockIdx.x * 128;
    const int tid  = threadIdx.x;
    const int wid  = tid >> 5;
    const int lane = tid & 31;
    const int grp  = lane >> 2;
    const int qid  = lane & 3;
    const int widm = wid & 1, widn = wid >> 1;
    const int warp_m = widm * 64, warp_n = widn * 32;
    __half* Sm = g_S + (size_t)bh * SS * SS;

    const uint32_t offA = LDSM_OFF_A(lane);
    const uint32_t offB = LDSM_OFF_B(lane);

#pragma unroll
    for (int t = 0; t < 4; t++) {
        int idx = tid + t * 256;
        int row = idx >> 3;
        int c8  = idx & 7;
        cp_async16(kBase + (uint32_t)(row * HST + c8 * 8) * 2,
                   g_Kh + (size_t)(b*SS + row) * DD + h*HW + c8*8);
    }
    cp_commit();

#pragma unroll
    for (int t = 0; t < 4; t++) {
        int idx = tid + t * 256;
        int row = idx >> 3;
        int c8  = idx & 7;
        uint4 v = *(const uint4*)(g_Qh + (size_t)(b*SS + q0 + row) * DD + h*HW + c8*8);
        *(uint4*)(Qs + row * HST + c8 * 8) = v;
    }

    float zlo[4] = {0.f,0.f,0.f,0.f}, zhi[4] = {0.f,0.f,0.f,0.f};

    for (int it = 0; it < 16; it++) {
        const int buf = it & 1;
        if (it + 1 < 16) {
            const int n1 = (it + 1) * 128;
#pragma unroll
            for (int t = 0; t < 4; t++) {
                int idx = tid + t * 256;
                int row = idx >> 3;
                int c8  = idx & 7;
                cp_async16(kBase + (uint32_t)((buf^1) * 128 * HST + row * HST + c8 * 8) * 2,
                           g_Kh + (size_t)(b*SS + n1 + row) * DD + h*HW + c8*8);
            }
        }
        cp_commit();
        cp_wait1();
        __syncthreads();

        float acc[4][4][4];
#pragma unroll
        for (int mt = 0; mt < 4; mt++)
#pragma unroll
            for (int nt = 0; nt < 4; nt++)
#pragma unroll
                for (int r = 0; r < 4; r++) acc[mt][nt][r] = 0.f;

        const uint32_t qT = qBase + warp_m * HSTB + offA;
        const uint32_t kT = kBase + buf * 128 * HSTB + warp_n * HSTB + offB;
#pragma unroll
        for (int ks = 0; ks < 4; ks++) {
            uint32_t af[4][4], bf[4][2];
#pragma unroll
            for (int mt = 0; mt < 4; mt++)
                ldsm_x4(af[mt][0], af[mt][1], af[mt][2], af[mt][3],
                        qT + mt * 16 * HSTB + ks * 32);
#pragma unroll
            for (int ntp = 0; ntp < 2; ntp++)
                ldsm_x4(bf[2*ntp][0], bf[2*ntp][1], bf[2*ntp+1][0], bf[2*ntp+1][1],
                        kT + ntp * 16 * HSTB + ks * 32);
#pragma unroll
            for (int mt = 0; mt < 4; mt++)
#pragma unroll
                for (int nt = 0; nt < 4; nt++)
                    mma_f16(acc[mt][nt], af[mt][0], af[mt][1], af[mt][2], af[mt][3],
                            bf[nt][0], bf[nt][1]);
        }

        const int n0 = it * 128;
#pragma unroll
        for (int mt = 0; mt < 4; mt++) {
            int r1 = warp_m + mt * 16 + grp;
            int r2 = r1 + 8;
#pragma unroll
            for (int nt = 0; nt < 4; nt++) {
                int col = n0 + warp_n + nt * 8 + 2 * qid;
                __half2 hA = hexp2s(acc[mt][nt][0], acc[mt][nt][1]);
                __half2 hB = hexp2s(acc[mt][nt][2], acc[mt][nt][3]);
                float2 fA = __half22float2(hA);
                float2 fB = __half22float2(hB);
                zlo[mt] += fA.x + fA.y;
                zhi[mt] += fB.x + fB.y;
                *(__half2*)(Sm + (size_t)(q0 + r1) * SS + col) = hA;
                *(__half2*)(Sm + (size_t)(q0 + r2) * SS + col) = hB;
            }
        }
        __syncthreads();
    }

#pragma unroll
    for (int o = 1; o <= 2; o <<= 1)
#pragma unroll
        for (int mt = 0; mt < 4; mt++) {
            zlo[mt] += __shfl_xor_sync(0xffffffffu, zlo[mt], o);
            zhi[mt] += __shfl_xor_sync(0xffffffffu, zhi[mt], o);
        }
    if (qid == 0) {
#pragma unroll
        for (int mt = 0; mt < 4; mt++) {
            sz[widn][warp_m + mt * 16 + grp]     = zlo[mt];
            sz[widn][warp_m + mt * 16 + grp + 8] = zhi[mt];
        }
    }
    __syncthreads();
    if (tid < 128) {
        float z = (sz[0][tid] + sz[1][tid]) + (sz[2][tid] + sz[3][tid]);
        g_Z[(size_t)bh * SS + q0 + tid] = z;
    }
}

// ============================================================================
// K3: PV — t = texp_h2(e*invZ) directly as half2 A-fragments; out = (t@V)/Z2
// ============================================================================
__global__ void __launch_bounds__(256, 2)
attn_pv_h(float* __restrict__ out) {
    extern __shared__ __half hsm3[];
    __half* Et = hsm3;                  // [2][128][HST]
    __half* Vt = hsm3 + 2 * 128 * HST;  // [2][64][HST]
    const uint32_t eBase = smem_u32(Et);
    const uint32_t vBase = smem_u32(Vt);

    const int bh = blockIdx.y;
    const int b  = bh >> 4, h = bh & 15;
    const int q0 = blockIdx.x * 128;
    const int tid  = threadIdx.x;
    const int wid  = tid >> 5;
    const int lane = tid & 31;
    const int grp  = lane >> 2;
    const int qid  = lane & 3;
    const __half* Sm = g_S + (size_t)bh * SS * SS;
    const __half* Vg = g_Vt + (size_t)bh * 64 * SS;

    const int rA = wid * 16 + grp;
    const int rB = rA + 8;
    const float invZa = 1.0f / g_Z[(size_t)bh * SS + q0 + rA];
    const float invZb = 1.0f / g_Z[(size_t)bh * SS + q0 + rB];
    const __half2 izA = __half2half2(__float2half(invZa));
    const __half2 izB = __half2half2(__float2half(invZb));

    const uint32_t offA = LDSM_OFF_A(lane);
    const uint32_t offB = LDSM_OFF_B(lane);

#pragma unroll
    for (int t = 0; t < 4; t++) {
        int idx = tid + t * 256;
        int er = idx >> 3, ec = idx & 7;
        cp_async16(eBase + (uint32_t)(er * HST + ec * 8) * 2,
                   Sm + (size_t)(q0 + er) * SS + ec * 8);
    }
#pragma unroll
    for (int t = 0; t < 2; t++) {
        int idx = tid + t * 256;
        int vr = idx >> 3, vc = idx & 7;
        cp_async16(vBase + (uint32_t)(vr * HST + vc * 8) * 2,
                   Vg + (size_t)vr * SS + vc * 8);
    }
    cp_commit();

    float accPV[8][4];
#pragma unroll
    for (int nt = 0; nt < 8; nt++)
#pragma unroll
        for (int r = 0; r < 4; r++) accPV[nt][r] = 0.f;
    float z2a = 0.f, z2b = 0.f;

    for (int it = 0; it < 32; it++) {
        const int buf = it & 1;
        if (it + 1 < 32) {
            const int k1 = (it + 1) * 64;
#pragma unroll
            for (int t = 0; t < 4; t++) {
                int idx = tid + t * 256;
                int er = idx >> 3, ec = idx & 7;
                cp_async16(eBase + (uint32_t)((buf^1) * 128 * HST + er * HST + ec * 8) * 2,
                           Sm + (size_t)(q0 + er) * SS + k1 + ec * 8);
            }
#pragma unroll
            for (int t = 0; t < 2; t++) {
                int idx = tid + t * 256;
                int vr = idx >> 3, vc = idx & 7;
                cp_async16(vBase + (uint32_t)((buf^1) * 64 * HST + vr * HST + vc * 8) * 2,
                           Vg + (size_t)vr * SS + k1 + vc * 8);
            }
        }
        cp_commit();
        cp_wait1();
        __syncthreads();

        const uint32_t eT = eBase + buf * 128 * HSTB + wid * 16 * HSTB + offA;
        const uint32_t vT = vBase + buf * 64 * HSTB + offB;

#pragma unroll
        for (int ks = 0; ks < 4; ks++) {
            // E fragment: r0=(rA,k), r1=(rB,k), r2=(rA,k+8), r3=(rB,k+8)
            uint32_t e0, e1, e2, e3;
            ldsm_x4(e0, e1, e2, e3, eT + ks * 32);
            __half2 tA0 = texp_h2(*(__half2*)&e0, izA);
            __half2 tB0 = texp_h2(*(__half2*)&e1, izB);
            __half2 tA1 = texp_h2(*(__half2*)&e2, izA);
            __half2 tB1 = texp_h2(*(__half2*)&e3, izB);
            float2 za = __half22float2(__hadd2(tA0, tA1));
            float2 zb = __half22float2(__hadd2(tB0, tB1));
            z2a += za.x + za.y;
            z2b += zb.x + zb.y;
            uint32_t a0 = *(uint32_t*)&tA0, a1 = *(uint32_t*)&tB0;
            uint32_t a2 = *(uint32_t*)&tA1, a3 = *(uint32_t*)&tB1;

            uint32_t bf[8][2];
#pragma unroll
            for (int ntp = 0; ntp < 4; ntp++)
                ldsm_x4(bf[2*ntp][0], bf[2*ntp][1], bf[2*ntp+1][0], bf[2*ntp+1][1],
                        vT + ntp * 16 * HSTB + ks * 32);
#pragma unroll
            for (int nt = 0; nt < 8; nt++)
                mma_f16(accPV[nt], a0, a1, a2, a3, bf[nt][0], bf[nt][1]);
        }
        __syncthreads();
    }

#pragma unroll
    for (int o = 1; o <= 2; o <<= 1) {
        z2a += __shfl_xor_sync(0xffffffffu, z2a, o);
        z2b += __shfl_xor_sync(0xffffffffu, z2b, o);
    }
    const float ra = 1.0f / z2a;
    const float rb = 1.0f / z2b;

#pragma unroll
    for (int nt = 0; nt < 8; nt++) {
        int col = h * HW + nt * 8 + 2 * qid;
        *(float2*)(out + (size_t)(b*SS + q0 + rA) * DD + col) =
            make_float2(accPV[nt][0] * ra, accPV[nt][1] * ra);
        *(float2*)(out + (size_t)(b*SS + q0 + rB) * DD + col) =
            make_float2(accPV[nt][2] * rb, accPV[nt][3] * rb);
    }
}

// ---------------- launch -----------------------------------------------------
extern "C" void kernel_launch(void* const* d_in, const int* in_sizes, int n_in,
                              void* d_out, int out_size) {
    const float* x  = (const float*)d_in[0];
    const float* Wq = (const float*)d_in[1];
    const float* bq = (const float*)d_in[2];
    const float* Wk = (const float*)d_in[3];
    const float* bk = (const float*)d_in[4];
    const float* Wv = (const float*)d_in[5];
    const float* bv = (const float*)d_in[6];
    float* out = (float*)d_out;

    const int smem_gemm = 4 * 128 * HST * sizeof(__half);               // 73728
    const int smem_sc   = 3 * 128 * HST * sizeof(__half);               // 55296
    const int smem_pv   = (2 * 128 + 2 * 64) * HST * sizeof(__half);    // 55296
    cudaFuncSetAttribute(gemm_h,
                         cudaFuncAttributeMaxDynamicSharedMemorySize, smem_gemm);
    cudaFuncSetAttribute(attn_scores_h,
                         cudaFuncAttributeMaxDynamicSharedMemorySize, smem_sc);
    cudaFuncSetAttribute(attn_pv_h,
                         cudaFuncAttributeMaxDynamicSharedMemorySize, smem_pv);

    to_half_k<<<dim3(512, 7), 256>>>(x, Wq, Wk, Wv);

    dim3 gproj(DD / 128, MM / 128, 3);          // (8, 32, 3)
    gemm_h<<<gproj, 256, smem_gemm>>>(bq, bk, bv);

    dim3 gs(SS / 128, BB * HH);                 // (16, 32)
    attn_scores_h<<<gs, 256, smem_sc>>>();
    attn_pv_h<<<gs, 256, smem_pv>>>(out);
}

// round 14
// speedup vs baseline: 3.1218x; 1.1546x over previous
#include <cuda_runtime.h>
#include <cuda_fp16.h>
#include <cstdint>
#include <math.h>

#define BB 2
#define SS 2048
#define DD 1024
#define HH 16
#define HW 64
#define MM (BB*SS)   // 4096

// ---------------- scratch (no cudaMalloc allowed) ---------------------------
__device__ __half g_xh[(size_t)MM * DD];                // 8 MB
__device__ __half g_Wh[3][(size_t)DD * DD];             // 6 MB
__device__ __half g_Qh[(size_t)MM * DD];                // 8 MB
__device__ __half g_Kh[(size_t)MM * DD];                // 8 MB
__device__ __half g_Vt[(size_t)MM * DD];                // 8 MB  V transposed per head: [bh][w][s]
__device__ unsigned char g_S8[(size_t)BB * HH * SS * SS]; // 128 MB (e^s, e4m3, permuted 16-k blocks)
__device__ float  g_Z [(size_t)BB * HH * SS];           // Z1

// ---------------- PTX helpers (non-arch-specific only) ----------------------
__device__ __forceinline__ void mma_f16(float c[4],
                                        uint32_t a0, uint32_t a1, uint32_t a2, uint32_t a3,
                                        uint32_t b0, uint32_t b1) {
    asm volatile(
        "mma.sync.aligned.m16n8k16.row.col.f32.f16.f16.f32 "
        "{%0,%1,%2,%3}, {%4,%5,%6,%7}, {%8,%9}, {%0,%1,%2,%3};"
        : "+f"(c[0]), "+f"(c[1]), "+f"(c[2]), "+f"(c[3])
        : "r"(a0), "r"(a1), "r"(a2), "r"(a3), "r"(b0), "r"(b1));
}
__device__ __forceinline__ void ldsm_x4(uint32_t& r0, uint32_t& r1,
                                        uint32_t& r2, uint32_t& r3, uint32_t addr) {
    asm volatile("ldmatrix.sync.aligned.m8n8.x4.shared.b16 {%0,%1,%2,%3}, [%4];"
                 : "=r"(r0), "=r"(r1), "=r"(r2), "=r"(r3) : "r"(addr));
}
__device__ __forceinline__ uint32_t smem_u32(const void* p) {
    uint32_t a;
    asm("{ .reg .u64 t; cvta.to.shared.u64 t, %1; cvt.u32.u64 %0, t; }"
        : "=r"(a) : "l"(p));
    return a;
}
__device__ __forceinline__ void cp_async16(uint32_t s, const void* g) {
    asm volatile("cp.async.cg.shared.global [%0], [%1], 16;" :: "r"(s), "l"(g));
}
__device__ __forceinline__ void cp_commit() {
    asm volatile("cp.async.commit_group;" ::: "memory");
}
__device__ __forceinline__ void cp_wait1() {
    asm volatile("cp.async.wait_group 1;" ::: "memory");
}

// ---------------- fp8 converters ---------------------------------------------
// pack two half2 pairs -> 4 e4m3 bytes (lo16 = first pair, hi16 = second pair)
__device__ __forceinline__ uint32_t cvt_h2_e4m3(__half2 lo, __half2 hi) {
    unsigned short a, b;
    asm("cvt.rn.satfinite.e4m3x2.f16x2 %0, %1;" : "=h"(a) : "r"(*(uint32_t*)&lo));
    asm("cvt.rn.satfinite.e4m3x2.f16x2 %0, %1;" : "=h"(b) : "r"(*(uint32_t*)&hi));
    return (uint32_t)a | ((uint32_t)b << 16);
}
__device__ __forceinline__ __half2 cvt_e4m3_h2(unsigned short v) {
    uint32_t r;
    asm("cvt.rn.f16x2.e4m3x2 %0, %1;" : "=r"(r) : "h"(v));
    return *(__half2*)&r;
}

// ---------------- half2 exp variants ----------------------------------------
__device__ __forceinline__ __half2 hexp2s(float s0, float s1) {
    const float C8 = 0.18033688f;            // 0.125 * log2(e)
    __half2 y2 = __floats2half2_rn(s0 * C8, s1 * C8);
    y2 = __hmin2(__hmax2(y2, __floats2half2_rn(-14.f, -14.f)),
                 __floats2half2_rn(14.f, 14.f));
    const __half2 magic = __floats2half2_rn(1536.f, 1536.f);
    __half2 z2 = __hadd2(y2, magic);
    __half2 n2 = __hsub2(z2, magic);
    __half2 f2 = __hsub2(y2, n2);
    __half2 p  = __floats2half2_rn(0.00961813f, 0.00961813f);
    p = __hfma2(p, f2, __floats2half2_rn(0.05550411f, 0.05550411f));
    p = __hfma2(p, f2, __floats2half2_rn(0.24022651f, 0.24022651f));
    p = __hfma2(p, f2, __floats2half2_rn(0.69314718f, 0.69314718f));
    p = __hfma2(p, f2, __floats2half2_rn(1.0f, 1.0f));
    uint32_t zb = *(uint32_t*)&z2;
    uint32_t sb = ((zb - 0x65F165F1u) & 0x001F001Fu) << 10;
    return __hmul2(p, *(__half2*)&sb);
}
__device__ __forceinline__ __half2 texp_h2(__half2 e2, __half2 iz2) {
    __half2 p = __hmul2(e2, iz2);
    __half2 r = __floats2half2_rn(4.1666668e-2f, 4.1666668e-2f);
    r = __hfma2(r, p, __floats2half2_rn(1.6666667e-1f, 1.6666667e-1f));
    r = __hfma2(r, p, __floats2half2_rn(0.5f, 0.5f));
    r = __hfma2(r, p, __floats2half2_rn(1.0f, 1.0f));
    r = __hfma2(r, p, __floats2half2_rn(1.0f, 1.0f));
    return r;
}

// ============================================================================
// K0: fp32 -> fp16 convert
// ============================================================================
__global__ void __launch_bounds__(256)
to_half_k(const float* __restrict__ x,  const float* __restrict__ Wq,
          const float* __restrict__ Wk, const float* __restrict__ Wv) {
    const int seg = blockIdx.y;
    const size_t idx = ((size_t)blockIdx.x * 256 + threadIdx.x) * 8;
    const float* src;
    __half* dst;
    if (seg < 4) { src = x + (size_t)seg * 1048576; dst = g_xh + (size_t)seg * 1048576; }
    else if (seg == 4) { src = Wq; dst = g_Wh[0]; }
    else if (seg == 5) { src = Wk; dst = g_Wh[1]; }
    else               { src = Wv; dst = g_Wh[2]; }
    float4 a = *(const float4*)(src + idx);
    float4 b = *(const float4*)(src + idx + 4);
    __half2 h0 = __floats2half2_rn(a.x, a.y);
    __half2 h1 = __floats2half2_rn(a.z, a.w);
    __half2 h2 = __floats2half2_rn(b.x, b.y);
    __half2 h3 = __floats2half2_rn(b.z, b.w);
    uint4 o;
    o.x = *(uint32_t*)&h0; o.y = *(uint32_t*)&h1;
    o.z = *(uint32_t*)&h2; o.w = *(uint32_t*)&h3;
    *(uint4*)(dst + idx) = o;
}

#define HST  72             // fp16 tile row stride in halves
#define HSTB (HST * 2)
#define ESTB 80             // fp8 E tile row stride in bytes (16-aligned)

#define LDSM_OFF_A(lane) ((uint32_t)((((lane) & 7) + (((lane) >> 3) & 1) * 8) * HSTB + ((lane) >> 4) * 16))
#define LDSM_OFF_B(lane) ((uint32_t)((((lane) & 7) + ((lane) >> 4) * 8) * HSTB + (((lane) >> 3) & 1) * 16))
#define LDSM_OFF_E(lane) ((uint32_t)((((lane) & 7) + (((lane) >> 3) & 1) * 8) * ESTB + ((lane) >> 4) * 16))

// ============================================================================
// K1: fp16 m16n8k16 GEMM  C = X @ W^T + b. CTA 128x128, BK=64, 8 warps (2m x 4n)
// ============================================================================
__global__ void __launch_bounds__(256, 2)
gemm_h(const float* __restrict__ bq, const float* __restrict__ bk,
       const float* __restrict__ bv) {
    const int which = blockIdx.z;
    const __half* W    = g_Wh[which];
    const float* bias  = (which == 0) ? bq : (which == 1) ? bk : bv;

    extern __shared__ __half hsm[];
    __half* At = hsm;                  // [2][128][HST]
    __half* Bt = hsm + 2 * 128 * HST;  // [2][128][HST]
    const uint32_t aBase = smem_u32(At);
    const uint32_t bBase = smem_u32(Bt);

    const int tid  = threadIdx.x;
    const int wid  = tid >> 5;
    const int lane = tid & 31;
    const int qid  = lane & 3;
    const int m0 = blockIdx.y * 128;
    const int n0 = blockIdx.x * 128;
    const int warp_m = (wid & 1) * 64;
    const int warp_n = (wid >> 1) * 32;
    const int grp  = lane >> 2;

    const uint32_t offA = LDSM_OFF_A(lane);
    const uint32_t offB = LDSM_OFF_B(lane);

#pragma unroll
    for (int t = 0; t < 4; t++) {
        int idx = tid + t * 256;
        int row = idx >> 3;
        int c8  = idx & 7;
        cp_async16(aBase + (uint32_t)(row * HST + c8 * 8) * 2,
                   g_xh + (size_t)(m0 + row) * DD + c8 * 8);
        cp_async16(bBase + (uint32_t)(row * HST + c8 * 8) * 2,
                   W + (size_t)(n0 + row) * DD + c8 * 8);
    }
    cp_commit();

    float acc[4][4][4];
#pragma unroll
    for (int mt = 0; mt < 4; mt++)
#pragma unroll
        for (int nt = 0; nt < 4; nt++)
#pragma unroll
            for (int r = 0; r < 4; r++) acc[mt][nt][r] = 0.f;

    for (int kc = 0; kc < 16; kc++) {
        const int buf = kc & 1;
        if (kc + 1 < 16) {
            const int k1 = (kc + 1) * 64;
#pragma unroll
            for (int t = 0; t < 4; t++) {
                int idx = tid + t * 256;
                int row = idx >> 3;
                int c8  = idx & 7;
                cp_async16(aBase + (uint32_t)((buf^1) * 128 * HST + row * HST + c8 * 8) * 2,
                           g_xh + (size_t)(m0 + row) * DD + k1 + c8 * 8);
                cp_async16(bBase + (uint32_t)((buf^1) * 128 * HST + row * HST + c8 * 8) * 2,
                           W + (size_t)(n0 + row) * DD + k1 + c8 * 8);
            }
        }
        cp_commit();
        cp_wait1();
        __syncthreads();

        const uint32_t aT = aBase + buf * 128 * HSTB + warp_m * HSTB + offA;
        const uint32_t bT = bBase + buf * 128 * HSTB + warp_n * HSTB + offB;
#pragma unroll
        for (int ks = 0; ks < 4; ks++) {
            uint32_t af[4][4], bf[4][2];
#pragma unroll
            for (int mt = 0; mt < 4; mt++)
                ldsm_x4(af[mt][0], af[mt][1], af[mt][2], af[mt][3],
                        aT + mt * 16 * HSTB + ks * 32);
#pragma unroll
            for (int ntp = 0; ntp < 2; ntp++)
                ldsm_x4(bf[2*ntp][0], bf[2*ntp][1], bf[2*ntp+1][0], bf[2*ntp+1][1],
                        bT + ntp * 16 * HSTB + ks * 32);
#pragma unroll
            for (int mt = 0; mt < 4; mt++)
#pragma unroll
                for (int nt = 0; nt < 4; nt++)
                    mma_f16(acc[mt][nt], af[mt][0], af[mt][1], af[mt][2], af[mt][3],
                            bf[nt][0], bf[nt][1]);
        }
        __syncthreads();
    }

    if (which < 2) {
        __half* C = (which == 0) ? g_Qh : g_Kh;
#pragma unroll
        for (int mt = 0; mt < 4; mt++) {
#pragma unroll
            for (int nt = 0; nt < 4; nt++) {
                int col = n0 + warp_n + nt * 8 + 2 * qid;
                float bx = bias[col], by = bias[col + 1];
                int r0 = m0 + warp_m + mt * 16 + grp;
                __half2 o0 = __floats2half2_rn(acc[mt][nt][0] + bx, acc[mt][nt][1] + by);
                __half2 o1 = __floats2half2_rn(acc[mt][nt][2] + bx, acc[mt][nt][3] + by);
                *(__half2*)(C + (size_t)r0 * DD + col) = o0;
                *(__half2*)(C + (size_t)(r0 + 8) * DD + col) = o1;
            }
        }
    } else {
#pragma unroll
        for (int mt = 0; mt < 4; mt++) {
#pragma unroll
            for (int nt = 0; nt < 4; nt++) {
                int col = n0 + warp_n + nt * 8 + 2 * qid;
                float bx = bias[col], by = bias[col + 1];
                int r0 = m0 + warp_m + mt * 16 + grp;
                int hh = col >> 6, w = col & 63;
                int b1 = r0 >> 11, s1 = r0 & 2047;
                size_t base = ((size_t)(b1 * 16 + hh) * 64);
                g_Vt[(base + w    ) * SS + s1]     = __float2half(acc[mt][nt][0] + bx);
                g_Vt[(base + w + 1) * SS + s1]     = __float2half(acc[mt][nt][1] + by);
                g_Vt[(base + w    ) * SS + s1 + 8] = __float2half(acc[mt][nt][2] + bx);
                g_Vt[(base + w + 1) * SS + s1 + 8] = __float2half(acc[mt][nt][3] + by);
            }
        }
    }
}

// ============================================================================
// K2: scores — e = exp(s/8) -> g_S8 (e4m3, permuted 16-k blocks), Z1 -> g_Z
// Permutation per 16-k block: bytes 4q{+0,+1} = k{2q,2q+1}; 4q{+2,+3} = k{2q+8,2q+9}
// ============================================================================
__global__ void __launch_bounds__(256, 2)
attn_scores_h() {
    extern __shared__ __half hsm2[];
    __half* Qs = hsm2;                  // [128][HST]
    __half* Kt = hsm2 + 128 * HST;      // [2][128][HST]
    __shared__ float sz[4][128];
    const uint32_t qBase = smem_u32(Qs);
    const uint32_t kBase = smem_u32(Kt);

    const int bh = blockIdx.y;
    const int b  = bh >> 4, h = bh & 15;
    const int q0 = blockIdx.x * 128;
    const int tid  = threadIdx.x;
    const int wid  = tid >> 5;
    const int lane = tid & 31;
    const int grp  = lane >> 2;
    const int qid  = lane & 3;
    const int widm = wid & 1, widn = wid >> 1;
    const int warp_m = widm * 64, warp_n = widn * 32;
    unsigned char* Sm8 = g_S8 + (size_t)bh * SS * SS;

    const uint32_t offA = LDSM_OFF_A(lane);
    const uint32_t offB = LDSM_OFF_B(lane);

#pragma unroll
    for (int t = 0; t < 4; t++) {
        int idx = tid + t * 256;
        int row = idx >> 3;
        int c8  = idx & 7;
        cp_async16(kBase + (uint32_t)(row * HST + c8 * 8) * 2,
                   g_Kh + (size_t)(b*SS + row) * DD + h*HW + c8*8);
    }
    cp_commit();

#pragma unroll
    for (int t = 0; t < 4; t++) {
        int idx = tid + t * 256;
        int row = idx >> 3;
        int c8  = idx & 7;
        uint4 v = *(const uint4*)(g_Qh + (size_t)(b*SS + q0 + row) * DD + h*HW + c8*8);
        *(uint4*)(Qs + row * HST + c8 * 8) = v;
    }

    float zlo[4] = {0.f,0.f,0.f,0.f}, zhi[4] = {0.f,0.f,0.f,0.f};

    for (int it = 0; it < 16; it++) {
        const int buf = it & 1;
        if (it + 1 < 16) {
            const int n1 = (it + 1) * 128;
#pragma unroll
            for (int t = 0; t < 4; t++) {
                int idx = tid + t * 256;
                int row = idx >> 3;
                int c8  = idx & 7;
                cp_async16(kBase + (uint32_t)((buf^1) * 128 * HST + row * HST + c8 * 8) * 2,
                           g_Kh + (size_t)(b*SS + n1 + row) * DD + h*HW + c8*8);
            }
        }
        cp_commit();
        cp_wait1();
        __syncthreads();

        float acc[4][4][4];
#pragma unroll
        for (int mt = 0; mt < 4; mt++)
#pragma unroll
            for (int nt = 0; nt < 4; nt++)
#pragma unroll
                for (int r = 0; r < 4; r++) acc[mt][nt][r] = 0.f;

        const uint32_t qT = qBase + warp_m * HSTB + offA;
        const uint32_t kT = kBase + buf * 128 * HSTB + warp_n * HSTB + offB;
#pragma unroll
        for (int ks = 0; ks < 4; ks++) {
            uint32_t af[4][4], bf[4][2];
#pragma unroll
            for (int mt = 0; mt < 4; mt++)
                ldsm_x4(af[mt][0], af[mt][1], af[mt][2], af[mt][3],
                        qT + mt * 16 * HSTB + ks * 32);
#pragma unroll
            for (int ntp = 0; ntp < 2; ntp++)
                ldsm_x4(bf[2*ntp][0], bf[2*ntp][1], bf[2*ntp+1][0], bf[2*ntp+1][1],
                        kT + ntp * 16 * HSTB + ks * 32);
#pragma unroll
            for (int mt = 0; mt < 4; mt++)
#pragma unroll
                for (int nt = 0; nt < 4; nt++)
                    mma_f16(acc[mt][nt], af[mt][0], af[mt][1], af[mt][2], af[mt][3],
                            bf[nt][0], bf[nt][1]);
        }

        const int n0 = it * 128;
#pragma unroll
        for (int mt = 0; mt < 4; mt++) {
            int r1 = warp_m + mt * 16 + grp;
            int r2 = r1 + 8;
#pragma unroll
            for (int ntp = 0; ntp < 2; ntp++) {
                const float* aE = acc[mt][2*ntp];      // k_local = 2qid (+0,+1)
                const float* aO = acc[mt][2*ntp+1];    // k_local = 8+2qid (+0,+1)
                __half2 hAe = hexp2s(aE[0], aE[1]);
                __half2 hAo = hexp2s(aO[0], aO[1]);
                __half2 hBe = hexp2s(aE[2], aE[3]);
                __half2 hBo = hexp2s(aO[2], aO[3]);
                float2 f;
                f = __half22float2(__hadd2(hAe, hAo)); zlo[mt] += f.x + f.y;
                f = __half22float2(__hadd2(hBe, hBo)); zhi[mt] += f.x + f.y;
                uint32_t wA = cvt_h2_e4m3(hAe, hAo);
                uint32_t wB = cvt_h2_e4m3(hBe, hBo);
                int off = n0 + warp_n + ntp * 16 + 4 * qid;
                *(uint32_t*)(Sm8 + (size_t)(q0 + r1) * SS + off) = wA;
                *(uint32_t*)(Sm8 + (size_t)(q0 + r2) * SS + off) = wB;
            }
        }
        __syncthreads();
    }

#pragma unroll
    for (int o = 1; o <= 2; o <<= 1)
#pragma unroll
        for (int mt = 0; mt < 4; mt++) {
            zlo[mt] += __shfl_xor_sync(0xffffffffu, zlo[mt], o);
            zhi[mt] += __shfl_xor_sync(0xffffffffu, zhi[mt], o);
        }
    if (qid == 0) {
#pragma unroll
        for (int mt = 0; mt < 4; mt++) {
            sz[widn][warp_m + mt * 16 + grp]     = zlo[mt];
            sz[widn][warp_m + mt * 16 + grp + 8] = zhi[mt];
        }
    }
    __syncthreads();
    if (tid < 128) {
        float z = (sz[0][tid] + sz[1][tid]) + (sz[2][tid] + sz[3][tid]);
        g_Z[(size_t)bh * SS + q0 + tid] = z;
    }
}

// ============================================================================
// K3: PV — E (fp8, permuted) via one ldmatrix per 2 k-steps; t = texp_h2;
// out = (t @ V)/Z2.  V fp16 from g_Vt.  8 warps all-m.
// ============================================================================
__global__ void __launch_bounds__(256, 2)
attn_pv_h(float* __restrict__ out) {
    extern __shared__ __half hsm3[];
    unsigned char* Et = (unsigned char*)hsm3;          // [2][128][ESTB] fp8
    __half* Vt = (__half*)(Et + 2 * 128 * ESTB);       // [2][64][HST]
    const uint32_t eBase = smem_u32(Et);
    const uint32_t vBase = smem_u32(Vt);

    const int bh = blockIdx.y;
    const int b  = bh >> 4, h = bh & 15;
    const int q0 = blockIdx.x * 128;
    const int tid  = threadIdx.x;
    const int wid  = tid >> 5;
    const int lane = tid & 31;
    const int grp  = lane >> 2;
    const int qid  = lane & 3;
    const unsigned char* Sm8 = g_S8 + (size_t)bh * SS * SS;
    const __half* Vg = g_Vt + (size_t)bh * 64 * SS;

    const int rA = wid * 16 + grp;
    const int rB = rA + 8;
    const float invZa = 1.0f / g_Z[(size_t)bh * SS + q0 + rA];
    const float invZb = 1.0f / g_Z[(size_t)bh * SS + q0 + rB];
    const __half2 izA = __half2half2(__float2half(invZa));
    const __half2 izB = __half2half2(__float2half(invZb));

    const uint32_t offE = LDSM_OFF_E(lane);
    const uint32_t offB = LDSM_OFF_B(lane);

    // prologue: tile 0 (E: 128 rows x 64 bytes; V: 64 rows x 64 halves)
#pragma unroll
    for (int t = 0; t < 2; t++) {
        int idx = tid + t * 256;
        int er = idx >> 2, ec = idx & 3;
        cp_async16(eBase + (uint32_t)(er * ESTB + ec * 16),
                   Sm8 + (size_t)(q0 + er) * SS + ec * 16);
    }
#pragma unroll
    for (int t = 0; t < 2; t++) {
        int idx = tid + t * 256;
        int vr = idx >> 3, vc = idx & 7;
        cp_async16(vBase + (uint32_t)(vr * HST + vc * 8) * 2,
                   Vg + (size_t)vr * SS + vc * 8);
    }
    cp_commit();

    float accPV[8][4];
#pragma unroll
    for (int nt = 0; nt < 8; nt++)
#pragma unroll
        for (int r = 0; r < 4; r++) accPV[nt][r] = 0.f;
    float z2a = 0.f, z2b = 0.f;

    for (int it = 0; it < 32; it++) {
        const int buf = it & 1;
        if (it + 1 < 32) {
            const int k1 = (it + 1) * 64;
#pragma unroll
            for (int t = 0; t < 2; t++) {
                int idx = tid + t * 256;
                int er = idx >> 2, ec = idx & 3;
                cp_async16(eBase + (uint32_t)((buf^1) * 128 * ESTB + er * ESTB + ec * 16),
                           Sm8 + (size_t)(q0 + er) * SS + k1 + ec * 16);
            }
#pragma unroll
            for (int t = 0; t < 2; t++) {
                int idx = tid + t * 256;
                int vr = idx >> 3, vc = idx & 7;
                cp_async16(vBase + (uint32_t)((buf^1) * 64 * HST + vr * HST + vc * 8) * 2,
                           Vg + (size_t)vr * SS + k1 + vc * 8);
            }
        }
        cp_commit();
        cp_wait1();
        __syncthreads();

        const uint32_t eT = eBase + buf * 128 * ESTB + wid * 16 * ESTB + offE;
        const uint32_t vT = vBase + buf * 64 * HSTB + offB;

#pragma unroll
        for (int kp = 0; kp < 2; kp++) {
            // one ldmatrix covers rows rA/rB x 32 k (2 MMA k-steps)
            uint32_t e0, e1, e2, e3;
            ldsm_x4(e0, e1, e2, e3, eT + kp * 32);
#pragma unroll
            for (int j = 0; j < 2; j++) {
                uint32_t ra = (j == 0) ? e0 : e2;    // row rA: lo=a0-pair, hi=a2-pair
                uint32_t rb = (j == 0) ? e1 : e3;    // row rB
                __half2 tA0 = texp_h2(cvt_e4m3_h2((unsigned short)(ra & 0xFFFF)), izA);
                __half2 tA1 = texp_h2(cvt_e4m3_h2((unsigned short)(ra >> 16)),    izA);
                __half2 tB0 = texp_h2(cvt_e4m3_h2((unsigned short)(rb & 0xFFFF)), izB);
                __half2 tB1 = texp_h2(cvt_e4m3_h2((unsigned short)(rb >> 16)),    izB);
                float2 za = __half22float2(__hadd2(tA0, tA1));
                float2 zb = __half22float2(__hadd2(tB0, tB1));
                z2a += za.x + za.y;
                z2b += zb.x + zb.y;
                uint32_t a0 = *(uint32_t*)&tA0, a1 = *(uint32_t*)&tB0;
                uint32_t a2 = *(uint32_t*)&tA1, a3 = *(uint32_t*)&tB1;

                const int ks = kp * 2 + j;
                uint32_t bf[8][2];
#pragma unroll
                for (int ntp = 0; ntp < 4; ntp++)
                    ldsm_x4(bf[2*ntp][0], bf[2*ntp][1], bf[2*ntp+1][0], bf[2*ntp+1][1],
                            vT + ntp * 16 * HSTB + ks * 32);
#pragma unroll
                for (int nt = 0; nt < 8; nt++)
                    mma_f16(accPV[nt], a0, a1, a2, a3, bf[nt][0], bf[nt][1]);
            }
        }
        __syncthreads();
    }

#pragma unroll
    for (int o = 1; o <= 2; o <<= 1) {
        z2a += __shfl_xor_sync(0xffffffffu, z2a, o);
        z2b += __shfl_xor_sync(0xffffffffu, z2b, o);
    }
    const float ra = 1.0f / z2a;
    const float rb = 1.0f / z2b;

#pragma unroll
    for (int nt = 0; nt < 8; nt++) {
        int col = h * HW + nt * 8 + 2 * qid;
        *(float2*)(out + (size_t)(b*SS + q0 + rA) * DD + col) =
            make_float2(accPV[nt][0] * ra, accPV[nt][1] * ra);
        *(float2*)(out + (size_t)(b*SS + q0 + rB) * DD + col) =
            make_float2(accPV[nt][2] * rb, accPV[nt][3] * rb);
    }
}

// ---------------- launch -----------------------------------------------------
extern "C" void kernel_launch(void* const* d_in, const int* in_sizes, int n_in,
                              void* d_out, int out_size) {
    const float* x  = (const float*)d_in[0];
    const float* Wq = (const float*)d_in[1];
    const float* bq = (const float*)d_in[2];
    const float* Wk = (const float*)d_in[3];
    const float* bk = (const float*)d_in[4];
    const float* Wv = (const float*)d_in[5];
    const float* bv = (const float*)d_in[6];
    float* out = (float*)d_out;

    const int smem_gemm = 4 * 128 * HST * sizeof(__half);               // 73728
    const int smem_sc   = 3 * 128 * HST * sizeof(__half);               // 55296
    const int smem_pv   = 2 * 128 * ESTB + 2 * 64 * HST * sizeof(__half); // 38912
    cudaFuncSetAttribute(gemm_h,
                         cudaFuncAttributeMaxDynamicSharedMemorySize, smem_gemm);
    cudaFuncSetAttribute(attn_scores_h,
                         cudaFuncAttributeMaxDynamicSharedMemorySize, smem_sc);
    cudaFuncSetAttribute(attn_pv_h,
                         cudaFuncAttributeMaxDynamicSharedMemorySize, smem_pv);

    to_half_k<<<dim3(512, 7), 256>>>(x, Wq, Wk, Wv);

    dim3 gproj(DD / 128, MM / 128, 3);          // (8, 32, 3)
    gemm_h<<<gproj, 256, smem_gemm>>>(bq, bk, bv);

    dim3 gs(SS / 128, BB * HH);                 // (16, 32)
    attn_scores_h<<<gs, 256, smem_sc>>>();
    attn_pv_h<<<gs, 256, smem_pv>>>(out);
}